// round 4
// baseline (speedup 1.0000x reference)
#include <cuda_runtime.h>
#include <cuda_bf16.h>
#include <math.h>
#include <mma.h>

using namespace nvcuda;

// Problem constants
#define Bv 4
#define Tv 2048
#define Cv 1024
#define Hv 16
#define HDv 64
#define Mv (Bv * Tv)          // 8192 rows
#define QKV_N (3 * Cv)        // 3072

// Scratch (allocation-free rule: __device__ globals)
__device__ float g_qkv[Mv * QKV_N];   // [B*T, 3C] : q | k | v
__device__ float g_y[Mv * Cv];        // attention output [B*T, C]
__device__ float g_rope[2 * Tv * 32]; // [cos|sin][t][freq], bf16-rounded

// ---------------------------------------------------------------------------
// Rope table: cos/sin(t * 10000^(-i/32)) computed in double (fast-math-proof),
// rounded to fp32 then bf16 (matching reference), stored as fp32.
// ---------------------------------------------------------------------------
__global__ void rope_table_kernel(float* __restrict__ rope)
{
    int idx = blockIdx.x * blockDim.x + threadIdx.x;   // t*32 + i
    if (idx >= Tv * 32) return;
    int t = idx >> 5;
    int i = idx & 31;
    double inv_freq_d = exp(-(double)i * (9.210340371976184 / 32.0));
    float  inv_freq   = (float)inv_freq_d;
    float  ang        = (float)t * inv_freq;           // fp32 product like reference
    float  cf = (float)cos((double)ang);
    float  sf = (float)sin((double)ang);
    rope[idx]           = __bfloat162float(__float2bfloat16(cf));
    rope[Tv * 32 + idx] = __bfloat162float(__float2bfloat16(sf));
}

// ---------------------------------------------------------------------------
// tf32 hi/lo split helper (3xTF32 emulated fp32)
// ---------------------------------------------------------------------------
__device__ __forceinline__ void split4(const float4 v, float4& h, float4& l)
{
    h.x = wmma::__float_to_tf32(v.x); l.x = wmma::__float_to_tf32(v.x - h.x);
    h.y = wmma::__float_to_tf32(v.y); l.y = wmma::__float_to_tf32(v.y - h.y);
    h.z = wmma::__float_to_tf32(v.z); l.z = wmma::__float_to_tf32(v.z - h.z);
    h.w = wmma::__float_to_tf32(v.w); l.w = wmma::__float_to_tf32(v.w - h.w);
}

// ---------------------------------------------------------------------------
// GEMM (NT): C[M,N] = A[M,K] * B[N,K]^T, fp32 in/out. 3xTF32.
// BM=128, BN=128, BK=32, 256 threads = 8 warps (4x2), warp tile 32x64.
// ---------------------------------------------------------------------------
__global__ void __launch_bounds__(256) gemm_tf32_nt(
    const float* __restrict__ A, const float* __restrict__ B,
    float* __restrict__ C, int M, int N, int K)
{
    constexpr int BM = 128, BN = 128, BK = 32, LD = 36;  // LD*4B = 144B
    extern __shared__ __align__(16) float smem[];
    float* Ah = smem;                 // BM*LD
    float* Al = Ah + BM * LD;
    float* Bh = Al + BM * LD;
    float* Bl = Bh + BN * LD;

    const int tid = threadIdx.x;
    const int m0 = blockIdx.y * BM;
    const int n0 = blockIdx.x * BN;
    const int w  = tid >> 5;
    const int wm = w >> 1;     // 0..3
    const int wn = w & 1;      // 0..1

    wmma::fragment<wmma::accumulator, 16, 16, 8, float> acc[2][4];
#pragma unroll
    for (int i = 0; i < 2; i++)
#pragma unroll
        for (int j = 0; j < 4; j++)
            wmma::fill_fragment(acc[i][j], 0.0f);

    for (int k0 = 0; k0 < K; k0 += BK) {
#pragma unroll
        for (int idx = tid; idx < BM * BK / 4; idx += 256) {
            int r  = idx >> 3;
            int c4 = (idx & 7) * 4;
            float4 v = *(const float4*)&A[(size_t)(m0 + r) * K + k0 + c4];
            float4 h, l;
            split4(v, h, l);
            *(float4*)&Ah[r * LD + c4] = h;
            *(float4*)&Al[r * LD + c4] = l;
        }
#pragma unroll
        for (int idx = tid; idx < BN * BK / 4; idx += 256) {
            int r  = idx >> 3;
            int c4 = (idx & 7) * 4;
            float4 v = *(const float4*)&B[(size_t)(n0 + r) * K + k0 + c4];
            float4 h, l;
            split4(v, h, l);
            *(float4*)&Bh[r * LD + c4] = h;
            *(float4*)&Bl[r * LD + c4] = l;
        }
        __syncthreads();

#pragma unroll
        for (int kk = 0; kk < BK; kk += 8) {
            wmma::fragment<wmma::matrix_a, 16, 16, 8, wmma::precision::tf32, wmma::row_major> afh[2], afl[2];
            wmma::fragment<wmma::matrix_b, 16, 16, 8, wmma::precision::tf32, wmma::col_major> bfh[4], bfl[4];
#pragma unroll
            for (int i = 0; i < 2; i++) {
                wmma::load_matrix_sync(afh[i], &Ah[(wm * 32 + i * 16) * LD + kk], LD);
                wmma::load_matrix_sync(afl[i], &Al[(wm * 32 + i * 16) * LD + kk], LD);
            }
#pragma unroll
            for (int j = 0; j < 4; j++) {
                wmma::load_matrix_sync(bfh[j], &Bh[(wn * 64 + j * 16) * LD + kk], LD);
                wmma::load_matrix_sync(bfl[j], &Bl[(wn * 64 + j * 16) * LD + kk], LD);
            }
#pragma unroll
            for (int i = 0; i < 2; i++)
#pragma unroll
                for (int j = 0; j < 4; j++) {
                    wmma::mma_sync(acc[i][j], afh[i], bfl[j], acc[i][j]);
                    wmma::mma_sync(acc[i][j], afl[i], bfh[j], acc[i][j]);
                    wmma::mma_sync(acc[i][j], afh[i], bfh[j], acc[i][j]);
                }
        }
        __syncthreads();
    }

#pragma unroll
    for (int i = 0; i < 2; i++)
#pragma unroll
        for (int j = 0; j < 4; j++)
            wmma::store_matrix_sync(
                C + (size_t)(m0 + wm * 32 + i * 16) * N + n0 + wn * 64 + j * 16,
                acc[i][j], N, wmma::mem_row_major);
}

// ---------------------------------------------------------------------------
// Fused RMSNorm(HD=64) + rotary (reads precomputed bf16-rounded cos/sin).
// ---------------------------------------------------------------------------
__global__ void __launch_bounds__(512) norm_rope_kernel(
    float* __restrict__ qkv, const float* __restrict__ rope)
{
    const int bt   = blockIdx.x;
    const int t    = bt & (Tv - 1);
    const int warp = threadIdx.x >> 5;
    const int lane = threadIdx.x & 31;

    float* qp = qkv + (size_t)bt * QKV_N + warp * HDv;
    float c = rope[t * 32 + lane];
    float s = rope[Tv * 32 + t * 32 + lane];

#pragma unroll
    for (int p = 0; p < 2; p++) {   // p=0: q, p=1: k
        float* ptr = qp + p * Cv;
        float x1 = ptr[lane];
        float x2 = ptr[lane + 32];
        float ss = x1 * x1 + x2 * x2;
#pragma unroll
        for (int off = 16; off; off >>= 1)
            ss += __shfl_xor_sync(0xffffffffu, ss, off);
        float r = rsqrtf(ss * (1.0f / 64.0f) + 1.1920929e-07f);
        x1 *= r; x2 *= r;
        ptr[lane]      =  x1 * c + x2 * s;
        ptr[lane + 32] = -x1 * s + x2 * c;
    }
}

// ---------------------------------------------------------------------------
// Flash attention, tensor-core (3xTF32), causal, online softmax.
// Grid: (T/64, B*H). 256 threads = 8 warps; warp w owns a 16x32 slice of S/O
// (2 wmma 16x16 tiles). O accumulator lives in smem, rescaled per iteration.
// Smem buffers (LD=68 pad): Qh Ql Kh Kl Vh Vl Ph Pl O  (Ph doubles as S).
// ---------------------------------------------------------------------------
__global__ void __launch_bounds__(256) flash_tc_kernel(
    const float* __restrict__ qkv, float* __restrict__ y)
{
    constexpr int LD = 68;
    extern __shared__ __align__(16) float sm[];
    float* Qh = sm;
    float* Ql = Qh + 64 * LD;
    float* Kh = Ql + 64 * LD;
    float* Kl = Kh + 64 * LD;
    float* Vh = Kl + 64 * LD;
    float* Vl = Vh + 64 * LD;
    float* Ph = Vl + 64 * LD;   // S buffer, then P-hi
    float* Pl = Ph + 64 * LD;
    float* Ob = Pl + 64 * LD;

    const int qt  = gridDim.x - 1 - blockIdx.x;   // heavy tiles first
    const int bh  = blockIdx.y;
    const int b   = bh / Hv;
    const int h   = bh % Hv;
    const int tid = threadIdx.x;
    const int w   = tid >> 5;
    const int wm  = w >> 1;     // 0..3 : S/O tile row (16 rows)
    const int wn  = w & 1;      // 0..1 : S/O tile col pair (32 cols)
    const int ty  = tid >> 4;   // 0..15 (softmax phase: 4 rows each)
    const int tx  = tid & 15;   // 0..15 (softmax phase: 4 cols each)

    const size_t rowbase = (size_t)b * Tv;
    const int q0 = qt * 64;

    // Load Q tile once (split), zero O
    for (int idx = tid; idx < 64 * 16; idx += 256) {
        int r  = idx >> 4;
        int c4 = (idx & 15) * 4;
        float4 v = *(const float4*)&qkv[(rowbase + q0 + r) * (size_t)QKV_N + h * HDv + c4];
        float4 hi, lo;
        split4(v, hi, lo);
        *(float4*)&Qh[r * LD + c4] = hi;
        *(float4*)&Ql[r * LD + c4] = lo;
        *(float4*)&Ob[r * LD + c4] = make_float4(0.f, 0.f, 0.f, 0.f);
    }

    float m_i[4], l_i[4];
#pragma unroll
    for (int i = 0; i < 4; i++) { m_i[i] = -1e30f; l_i[i] = 0.0f; }

    for (int jt = 0; jt <= qt; jt++) {
        __syncthreads();   // prev iteration's PV done with Kh..Vl, Ph, Pl

        // Load K,V tile (split)
        for (int idx = tid; idx < 64 * 16; idx += 256) {
            int r  = idx >> 4;
            int c4 = (idx & 15) * 4;
            size_t roff = (rowbase + jt * 64 + r) * (size_t)QKV_N + h * HDv + c4;
            float4 kv = *(const float4*)(qkv + roff + Cv);
            float4 vv = *(const float4*)(qkv + roff + 2 * Cv);
            float4 hi, lo;
            split4(kv, hi, lo);
            *(float4*)&Kh[r * LD + c4] = hi;
            *(float4*)&Kl[r * LD + c4] = lo;
            split4(vv, hi, lo);
            *(float4*)&Vh[r * LD + c4] = hi;
            *(float4*)&Vl[r * LD + c4] = lo;
        }
        __syncthreads();

        // --- S = Q K^T (3xTF32) -> Ph (as S buffer) ---
        {
            wmma::fragment<wmma::accumulator, 16, 16, 8, float> sacc[2];
            wmma::fill_fragment(sacc[0], 0.0f);
            wmma::fill_fragment(sacc[1], 0.0f);
#pragma unroll
            for (int kk = 0; kk < 64; kk += 8) {
                wmma::fragment<wmma::matrix_a, 16, 16, 8, wmma::precision::tf32, wmma::row_major> afh, afl;
                wmma::fragment<wmma::matrix_b, 16, 16, 8, wmma::precision::tf32, wmma::col_major> bfh[2], bfl[2];
                wmma::load_matrix_sync(afh, &Qh[(wm * 16) * LD + kk], LD);
                wmma::load_matrix_sync(afl, &Ql[(wm * 16) * LD + kk], LD);
#pragma unroll
                for (int t = 0; t < 2; t++) {
                    wmma::load_matrix_sync(bfh[t], &Kh[(wn * 32 + t * 16) * LD + kk], LD);
                    wmma::load_matrix_sync(bfl[t], &Kl[(wn * 32 + t * 16) * LD + kk], LD);
                }
#pragma unroll
                for (int t = 0; t < 2; t++) {
                    wmma::mma_sync(sacc[t], afh, bfl[t], sacc[t]);
                    wmma::mma_sync(sacc[t], afl, bfh[t], sacc[t]);
                    wmma::mma_sync(sacc[t], afh, bfh[t], sacc[t]);
                }
            }
#pragma unroll
            for (int t = 0; t < 2; t++)
                wmma::store_matrix_sync(&Ph[(wm * 16) * LD + wn * 32 + t * 16],
                                        sacc[t], LD, wmma::mem_row_major);
        }
        __syncthreads();

        // --- softmax (threads): read S from Ph, rescale Ob, write Ph/Pl ---
        const bool diag = (jt == qt);
#pragma unroll
        for (int i = 0; i < 4; i++) {
            const int row = ty * 4 + i;
            float4 s4 = *(const float4*)&Ph[row * LD + tx * 4];
            float sv[4] = { s4.x, s4.y, s4.z, s4.w };
            float mx = -1e30f;
#pragma unroll
            for (int j = 0; j < 4; j++) {
                sv[j] *= 0.125f;          // 1/sqrt(64)
                if (diag && (tx * 4 + j > row)) sv[j] = -1e30f;
                mx = fmaxf(mx, sv[j]);
            }
#pragma unroll
            for (int off = 8; off; off >>= 1)
                mx = fmaxf(mx, __shfl_xor_sync(0xffffffffu, mx, off));
            float mn   = fmaxf(m_i[i], mx);
            float corr = expf(m_i[i] - mn);
            float pj[4];
            float sum = 0.0f;
#pragma unroll
            for (int j = 0; j < 4; j++) {
                pj[j] = expf(sv[j] - mn);
                sum += pj[j];
            }
#pragma unroll
            for (int off = 8; off; off >>= 1)
                sum += __shfl_xor_sync(0xffffffffu, sum, off);
            l_i[i] = l_i[i] * corr + sum;
            m_i[i] = mn;

            // rescale O slice (this thread owns row, cols tx*4..+3)
            float4 o4 = *(const float4*)&Ob[row * LD + tx * 4];
            o4.x *= corr; o4.y *= corr; o4.z *= corr; o4.w *= corr;
            *(float4*)&Ob[row * LD + tx * 4] = o4;

            // write P hi/lo (tf32 split)
            float4 p4 = make_float4(pj[0], pj[1], pj[2], pj[3]);
            float4 phi, plo;
            split4(p4, phi, plo);
            *(float4*)&Ph[row * LD + tx * 4] = phi;
            *(float4*)&Pl[row * LD + tx * 4] = plo;
        }
        __syncthreads();

        // --- O += P V (3xTF32), acc in smem ---
        {
            wmma::fragment<wmma::accumulator, 16, 16, 8, float> oacc[2];
#pragma unroll
            for (int t = 0; t < 2; t++)
                wmma::load_matrix_sync(oacc[t], &Ob[(wm * 16) * LD + wn * 32 + t * 16],
                                       LD, wmma::mem_row_major);
#pragma unroll
            for (int kk = 0; kk < 64; kk += 8) {
                wmma::fragment<wmma::matrix_a, 16, 16, 8, wmma::precision::tf32, wmma::row_major> afh, afl;
                wmma::fragment<wmma::matrix_b, 16, 16, 8, wmma::precision::tf32, wmma::row_major> bfh[2], bfl[2];
                wmma::load_matrix_sync(afh, &Ph[(wm * 16) * LD + kk], LD);
                wmma::load_matrix_sync(afl, &Pl[(wm * 16) * LD + kk], LD);
#pragma unroll
                for (int t = 0; t < 2; t++) {
                    wmma::load_matrix_sync(bfh[t], &Vh[kk * LD + wn * 32 + t * 16], LD);
                    wmma::load_matrix_sync(bfl[t], &Vl[kk * LD + wn * 32 + t * 16], LD);
                }
#pragma unroll
                for (int t = 0; t < 2; t++) {
                    wmma::mma_sync(oacc[t], afh, bfl[t], oacc[t]);
                    wmma::mma_sync(oacc[t], afl, bfh[t], oacc[t]);
                    wmma::mma_sync(oacc[t], afh, bfh[t], oacc[t]);
                }
            }
#pragma unroll
            for (int t = 0; t < 2; t++)
                wmma::store_matrix_sync(&Ob[(wm * 16) * LD + wn * 32 + t * 16],
                                        oacc[t], LD, wmma::mem_row_major);
        }
    }
    __syncthreads();

    // Epilogue: normalize rows, write y[b, q, h*64 + c]
#pragma unroll
    for (int i = 0; i < 4; i++) {
        const int row = ty * 4 + i;
        float inv = 1.0f / l_i[i];
        float4 o4 = *(const float4*)&Ob[row * LD + tx * 4];
        o4.x *= inv; o4.y *= inv; o4.z *= inv; o4.w *= inv;
        *(float4*)&y[(rowbase + q0 + row) * (size_t)Cv + h * HDv + tx * 4] = o4;
    }
}

// ---------------------------------------------------------------------------
// Launcher (graph-capturable: kernel launches + attribute setup only)
// ---------------------------------------------------------------------------
extern "C" void kernel_launch(void* const* d_in, const int* in_sizes, int n_in,
                              void* d_out, int out_size)
{
    const float* x      = (const float*)d_in[0];
    const float* w_attn = (const float*)d_in[1];
    const float* w_proj = (const float*)d_in[2];
    float* out = (float*)d_out;

    float *qkv_p = nullptr, *y_p = nullptr, *rope_p = nullptr;
    cudaGetSymbolAddress((void**)&qkv_p, g_qkv);
    cudaGetSymbolAddress((void**)&y_p, g_y);
    cudaGetSymbolAddress((void**)&rope_p, g_rope);

    const int GEMM_SMEM = 4 * 128 * 36 * (int)sizeof(float);  // 73728 B
    cudaFuncSetAttribute(gemm_tf32_nt, cudaFuncAttributeMaxDynamicSharedMemorySize, GEMM_SMEM);

    // 0) rope table
    rope_table_kernel<<<(Tv * 32 + 255) / 256, 256>>>(rope_p);

    // 1) qkv = x @ w_attn^T   [8192,3072]
    gemm_tf32_nt<<<dim3(QKV_N / 128, Mv / 128), 256, GEMM_SMEM>>>(x, w_attn, qkv_p, Mv, QKV_N, Cv);

    // 2) RMSNorm + RoPE on q,k (in place)
    norm_rope_kernel<<<Mv, 512>>>(qkv_p, rope_p);

    // 3) Causal flash attention (tensor cores) -> g_y
    const int FLASH_SMEM = 9 * 64 * 68 * (int)sizeof(float);  // 156672 B
    cudaFuncSetAttribute(flash_tc_kernel, cudaFuncAttributeMaxDynamicSharedMemorySize, FLASH_SMEM);
    flash_tc_kernel<<<dim3(Tv / 64, Bv * Hv), 256, FLASH_SMEM>>>(qkv_p, y_p);

    // 4) out = y @ w_proj^T   [8192,1024]
    gemm_tf32_nt<<<dim3(Cv / 128, Mv / 128), 256, GEMM_SMEM>>>(y_p, w_proj, out, Mv, Cv, Cv);
}

// round 6
// speedup vs baseline: 2.7860x; 2.7860x over previous
#include <cuda_runtime.h>
#include <cuda_bf16.h>
#include <math.h>
#include <mma.h>

using namespace nvcuda;

// Problem constants
#define Bv 4
#define Tv 2048
#define Cv 1024
#define Hv 16
#define HDv 64
#define Mv (Bv * Tv)          // 8192 rows
#define QKV_N (3 * Cv)        // 3072

// Scratch (allocation-free rule: __device__ globals)
__device__ float g_qkv[Mv * QKV_N];   // [B*T, 3C] : q | k | v
__device__ float g_y[Mv * Cv];        // attention output [B*T, C]
__device__ float g_rope[2 * Tv * 32]; // [cos|sin][t][freq], bf16-rounded

// ---------------------------------------------------------------------------
// Rope table: cos/sin(t * 10000^(-i/32)) in double (fast-math-proof),
// rounded fp32 then bf16 (matching reference), stored fp32.
// ---------------------------------------------------------------------------
__global__ void rope_table_kernel(float* __restrict__ rope)
{
    int idx = blockIdx.x * blockDim.x + threadIdx.x;   // t*32 + i
    if (idx >= Tv * 32) return;
    int t = idx >> 5;
    int i = idx & 31;
    double inv_freq_d = exp(-(double)i * (9.210340371976184 / 32.0));
    float  inv_freq   = (float)inv_freq_d;
    float  ang        = (float)t * inv_freq;
    float  cf = (float)cos((double)ang);
    float  sf = (float)sin((double)ang);
    rope[idx]           = __bfloat162float(__float2bfloat16(cf));
    rope[Tv * 32 + idx] = __bfloat162float(__float2bfloat16(sf));
}

// ---------------------------------------------------------------------------
// bf16 hi/lo split helpers (3xBF16 emulated ~fp32: eff. precision ~2^-16)
// ---------------------------------------------------------------------------
__device__ __forceinline__ void bsplit4(const float4 v,
                                        __nv_bfloat16* __restrict__ h,
                                        __nv_bfloat16* __restrict__ l)
{
    __nv_bfloat16 hx = __float2bfloat16(v.x);
    __nv_bfloat16 hy = __float2bfloat16(v.y);
    __nv_bfloat16 hz = __float2bfloat16(v.z);
    __nv_bfloat16 hw = __float2bfloat16(v.w);
    h[0] = hx; h[1] = hy; h[2] = hz; h[3] = hw;
    l[0] = __float2bfloat16(v.x - __bfloat162float(hx));
    l[1] = __float2bfloat16(v.y - __bfloat162float(hy));
    l[2] = __float2bfloat16(v.z - __bfloat162float(hz));
    l[3] = __float2bfloat16(v.w - __bfloat162float(hw));
}

// ---------------------------------------------------------------------------
// GEMM (NT): C[M,N] = A[M,K] * B[N,K]^T, fp32 in/out, 3xBF16 tensor cores.
// BM=128, BN=128, BK=32, 256 threads = 8 warps (4x2), warp tile 32x64.
// ---------------------------------------------------------------------------
__global__ void __launch_bounds__(256) gemm_bf16x3_nt(
    const float* __restrict__ A, const float* __restrict__ B,
    float* __restrict__ C, int M, int N, int K)
{
    constexpr int BM = 128, BN = 128, BK = 32, LD = 40;  // bf16 elems; 80B rows
    extern __shared__ __align__(16) char smraw[];
    __nv_bfloat16* Ah = (__nv_bfloat16*)smraw;           // BM*LD
    __nv_bfloat16* Al = Ah + BM * LD;
    __nv_bfloat16* Bh = Al + BM * LD;
    __nv_bfloat16* Bl = Bh + BN * LD;

    const int tid = threadIdx.x;
    const int m0 = blockIdx.y * BM;
    const int n0 = blockIdx.x * BN;
    const int w  = tid >> 5;
    const int wm = w >> 1;     // 0..3
    const int wn = w & 1;      // 0..1

    wmma::fragment<wmma::accumulator, 16, 16, 16, float> acc[2][4];
#pragma unroll
    for (int i = 0; i < 2; i++)
#pragma unroll
        for (int j = 0; j < 4; j++)
            wmma::fill_fragment(acc[i][j], 0.0f);

    for (int k0 = 0; k0 < K; k0 += BK) {
#pragma unroll
        for (int idx = tid; idx < BM * BK / 4; idx += 256) {
            int r  = idx >> 3;
            int c4 = (idx & 7) * 4;
            float4 v = *(const float4*)&A[(size_t)(m0 + r) * K + k0 + c4];
            bsplit4(v, &Ah[r * LD + c4], &Al[r * LD + c4]);
        }
#pragma unroll
        for (int idx = tid; idx < BN * BK / 4; idx += 256) {
            int r  = idx >> 3;
            int c4 = (idx & 7) * 4;
            float4 v = *(const float4*)&B[(size_t)(n0 + r) * K + k0 + c4];
            bsplit4(v, &Bh[r * LD + c4], &Bl[r * LD + c4]);
        }
        __syncthreads();

#pragma unroll
        for (int kk = 0; kk < BK; kk += 16) {
            wmma::fragment<wmma::matrix_a, 16, 16, 16, __nv_bfloat16, wmma::row_major> afh[2], afl[2];
            wmma::fragment<wmma::matrix_b, 16, 16, 16, __nv_bfloat16, wmma::col_major> bfh[4], bfl[4];
#pragma unroll
            for (int i = 0; i < 2; i++) {
                wmma::load_matrix_sync(afh[i], &Ah[(wm * 32 + i * 16) * LD + kk], LD);
                wmma::load_matrix_sync(afl[i], &Al[(wm * 32 + i * 16) * LD + kk], LD);
            }
#pragma unroll
            for (int j = 0; j < 4; j++) {
                wmma::load_matrix_sync(bfh[j], &Bh[(wn * 64 + j * 16) * LD + kk], LD);
                wmma::load_matrix_sync(bfl[j], &Bl[(wn * 64 + j * 16) * LD + kk], LD);
            }
#pragma unroll
            for (int i = 0; i < 2; i++)
#pragma unroll
                for (int j = 0; j < 4; j++) {
                    wmma::mma_sync(acc[i][j], afh[i], bfl[j], acc[i][j]);
                    wmma::mma_sync(acc[i][j], afl[i], bfh[j], acc[i][j]);
                    wmma::mma_sync(acc[i][j], afh[i], bfh[j], acc[i][j]);
                }
        }
        __syncthreads();
    }

#pragma unroll
    for (int i = 0; i < 2; i++)
#pragma unroll
        for (int j = 0; j < 4; j++)
            wmma::store_matrix_sync(
                C + (size_t)(m0 + wm * 32 + i * 16) * N + n0 + wn * 64 + j * 16,
                acc[i][j], N, wmma::mem_row_major);
}

// ---------------------------------------------------------------------------
// Fused RMSNorm(HD=64) + rotary (reads precomputed bf16-rounded cos/sin).
// ---------------------------------------------------------------------------
__global__ void __launch_bounds__(512) norm_rope_kernel(
    float* __restrict__ qkv, const float* __restrict__ rope)
{
    const int bt   = blockIdx.x;
    const int t    = bt & (Tv - 1);
    const int warp = threadIdx.x >> 5;
    const int lane = threadIdx.x & 31;

    float* qp = qkv + (size_t)bt * QKV_N + warp * HDv;
    float c = rope[t * 32 + lane];
    float s = rope[Tv * 32 + t * 32 + lane];

#pragma unroll
    for (int p = 0; p < 2; p++) {   // p=0: q, p=1: k
        float* ptr = qp + p * Cv;
        float x1 = ptr[lane];
        float x2 = ptr[lane + 32];
        float ss = x1 * x1 + x2 * x2;
#pragma unroll
        for (int off = 16; off; off >>= 1)
            ss += __shfl_xor_sync(0xffffffffu, ss, off);
        float r = rsqrtf(ss * (1.0f / 64.0f) + 1.1920929e-07f);
        x1 *= r; x2 *= r;
        ptr[lane]      =  x1 * c + x2 * s;
        ptr[lane + 32] = -x1 * s + x2 * c;
    }
}

// ---------------------------------------------------------------------------
// Flash attention, 3xBF16 tensor cores, causal, online softmax.
// Grid: (T/64, B*H). 256 thr = 8 warps; warp w owns 16x32 of S/O.
// O accumulator in smem fp32, rescaled per iteration.
// Smem ~106KB -> 2 CTAs/SM.
// ---------------------------------------------------------------------------
__global__ void __launch_bounds__(256) flash_bf16_kernel(
    const float* __restrict__ qkv, float* __restrict__ y)
{
    constexpr int LDB = 72;   // bf16 elems (144B rows)
    constexpr int LDF = 68;   // fp32 elems (272B rows)
    extern __shared__ __align__(16) char smraw[];
    __nv_bfloat16* Qh = (__nv_bfloat16*)smraw;    // 8 bf16 bufs of 64*LDB
    __nv_bfloat16* Ql = Qh + 64 * LDB;
    __nv_bfloat16* Kh = Ql + 64 * LDB;
    __nv_bfloat16* Kl = Kh + 64 * LDB;
    __nv_bfloat16* Vh = Kl + 64 * LDB;
    __nv_bfloat16* Vl = Vh + 64 * LDB;
    __nv_bfloat16* Ph = Vl + 64 * LDB;
    __nv_bfloat16* Pl = Ph + 64 * LDB;
    float* Sb = (float*)(Pl + 64 * LDB);          // 64*LDF fp32 (S scores)
    float* Ob = Sb + 64 * LDF;                    // 64*LDF fp32 (O accum)

    const int qt  = gridDim.x - 1 - blockIdx.x;   // heavy tiles first
    const int bh  = blockIdx.y;
    const int b   = bh / Hv;
    const int h   = bh % Hv;
    const int tid = threadIdx.x;
    const int w   = tid >> 5;
    const int wm  = w >> 1;     // 0..3 : S/O tile row (16 rows)
    const int wn  = w & 1;      // 0..1 : S/O tile col pair (32 cols)
    const int ty  = tid >> 4;   // 0..15 (softmax: 4 rows each)
    const int tx  = tid & 15;   // 0..15 (softmax: 4 cols each)

    const size_t rowbase = (size_t)b * Tv;
    const int q0 = qt * 64;

    // Load Q tile once (split), zero O
    for (int idx = tid; idx < 64 * 16; idx += 256) {
        int r  = idx >> 4;
        int c4 = (idx & 15) * 4;
        float4 v = *(const float4*)&qkv[(rowbase + q0 + r) * (size_t)QKV_N + h * HDv + c4];
        bsplit4(v, &Qh[r * LDB + c4], &Ql[r * LDB + c4]);
        *(float4*)&Ob[r * LDF + c4] = make_float4(0.f, 0.f, 0.f, 0.f);
    }

    float m_i[4], l_i[4];
#pragma unroll
    for (int i = 0; i < 4; i++) { m_i[i] = -1e30f; l_i[i] = 0.0f; }

    for (int jt = 0; jt <= qt; jt++) {
        __syncthreads();   // prev PV done with K/V/P buffers

        // Load K,V tile (split)
        for (int idx = tid; idx < 64 * 16; idx += 256) {
            int r  = idx >> 4;
            int c4 = (idx & 15) * 4;
            size_t roff = (rowbase + jt * 64 + r) * (size_t)QKV_N + h * HDv + c4;
            float4 kv = *(const float4*)(qkv + roff + Cv);
            float4 vv = *(const float4*)(qkv + roff + 2 * Cv);
            bsplit4(kv, &Kh[r * LDB + c4], &Kl[r * LDB + c4]);
            bsplit4(vv, &Vh[r * LDB + c4], &Vl[r * LDB + c4]);
        }
        __syncthreads();

        // --- S = Q K^T (3xBF16) -> Sb ---
        {
            wmma::fragment<wmma::accumulator, 16, 16, 16, float> sacc[2];
            wmma::fill_fragment(sacc[0], 0.0f);
            wmma::fill_fragment(sacc[1], 0.0f);
#pragma unroll
            for (int kk = 0; kk < 64; kk += 16) {
                wmma::fragment<wmma::matrix_a, 16, 16, 16, __nv_bfloat16, wmma::row_major> afh, afl;
                wmma::fragment<wmma::matrix_b, 16, 16, 16, __nv_bfloat16, wmma::col_major> bfh[2], bfl[2];
                wmma::load_matrix_sync(afh, &Qh[(wm * 16) * LDB + kk], LDB);
                wmma::load_matrix_sync(afl, &Ql[(wm * 16) * LDB + kk], LDB);
#pragma unroll
                for (int t = 0; t < 2; t++) {
                    wmma::load_matrix_sync(bfh[t], &Kh[(wn * 32 + t * 16) * LDB + kk], LDB);
                    wmma::load_matrix_sync(bfl[t], &Kl[(wn * 32 + t * 16) * LDB + kk], LDB);
                }
#pragma unroll
                for (int t = 0; t < 2; t++) {
                    wmma::mma_sync(sacc[t], afh, bfl[t], sacc[t]);
                    wmma::mma_sync(sacc[t], afl, bfh[t], sacc[t]);
                    wmma::mma_sync(sacc[t], afh, bfh[t], sacc[t]);
                }
            }
#pragma unroll
            for (int t = 0; t < 2; t++)
                wmma::store_matrix_sync(&Sb[(wm * 16) * LDF + wn * 32 + t * 16],
                                        sacc[t], LDF, wmma::mem_row_major);
        }
        __syncthreads();

        // --- softmax: read Sb, rescale Ob, write Ph/Pl (bf16 split) ---
        const bool diag = (jt == qt);
#pragma unroll
        for (int i = 0; i < 4; i++) {
            const int row = ty * 4 + i;
            float4 s4 = *(const float4*)&Sb[row * LDF + tx * 4];
            float sv[4] = { s4.x, s4.y, s4.z, s4.w };
            float mx = -1e30f;
#pragma unroll
            for (int j = 0; j < 4; j++) {
                sv[j] *= 0.125f;          // 1/sqrt(64)
                if (diag && (tx * 4 + j > row)) sv[j] = -1e30f;
                mx = fmaxf(mx, sv[j]);
            }
#pragma unroll
            for (int off = 8; off; off >>= 1)
                mx = fmaxf(mx, __shfl_xor_sync(0xffffffffu, mx, off));
            float mn   = fmaxf(m_i[i], mx);
            float corr = expf(m_i[i] - mn);
            float pj[4];
            float sum = 0.0f;
#pragma unroll
            for (int j = 0; j < 4; j++) {
                pj[j] = expf(sv[j] - mn);
                sum += pj[j];
            }
#pragma unroll
            for (int off = 8; off; off >>= 1)
                sum += __shfl_xor_sync(0xffffffffu, sum, off);
            l_i[i] = l_i[i] * corr + sum;
            m_i[i] = mn;

            // rescale O slice
            float4 o4 = *(const float4*)&Ob[row * LDF + tx * 4];
            o4.x *= corr; o4.y *= corr; o4.z *= corr; o4.w *= corr;
            *(float4*)&Ob[row * LDF + tx * 4] = o4;

            // write P hi/lo (bf16 split)
            float4 p4 = make_float4(pj[0], pj[1], pj[2], pj[3]);
            bsplit4(p4, &Ph[row * LDB + tx * 4], &Pl[row * LDB + tx * 4]);
        }
        __syncthreads();

        // --- O += P V (3xBF16), acc via smem round-trip ---
        {
            wmma::fragment<wmma::accumulator, 16, 16, 16, float> oacc[2];
#pragma unroll
            for (int t = 0; t < 2; t++)
                wmma::load_matrix_sync(oacc[t], &Ob[(wm * 16) * LDF + wn * 32 + t * 16],
                                       LDF, wmma::mem_row_major);
#pragma unroll
            for (int kk = 0; kk < 64; kk += 16) {
                wmma::fragment<wmma::matrix_a, 16, 16, 16, __nv_bfloat16, wmma::row_major> afh, afl;
                wmma::fragment<wmma::matrix_b, 16, 16, 16, __nv_bfloat16, wmma::row_major> bfh[2], bfl[2];
                wmma::load_matrix_sync(afh, &Ph[(wm * 16) * LDB + kk], LDB);
                wmma::load_matrix_sync(afl, &Pl[(wm * 16) * LDB + kk], LDB);
#pragma unroll
                for (int t = 0; t < 2; t++) {
                    wmma::load_matrix_sync(bfh[t], &Vh[kk * LDB + wn * 32 + t * 16], LDB);
                    wmma::load_matrix_sync(bfl[t], &Vl[kk * LDB + wn * 32 + t * 16], LDB);
                }
#pragma unroll
                for (int t = 0; t < 2; t++) {
                    wmma::mma_sync(oacc[t], afh, bfl[t], oacc[t]);
                    wmma::mma_sync(oacc[t], afl, bfh[t], oacc[t]);
                    wmma::mma_sync(oacc[t], afh, bfh[t], oacc[t]);
                }
            }
#pragma unroll
            for (int t = 0; t < 2; t++)
                wmma::store_matrix_sync(&Ob[(wm * 16) * LDF + wn * 32 + t * 16],
                                        oacc[t], LDF, wmma::mem_row_major);
        }
    }
    __syncthreads();

    // Epilogue: normalize rows, write y[b, q, h*64 + c]
#pragma unroll
    for (int i = 0; i < 4; i++) {
        const int row = ty * 4 + i;
        float inv = 1.0f / l_i[i];
        float4 o4 = *(const float4*)&Ob[row * LDF + tx * 4];
        o4.x *= inv; o4.y *= inv; o4.z *= inv; o4.w *= inv;
        *(float4*)&y[(rowbase + q0 + row) * (size_t)Cv + h * HDv + tx * 4] = o4;
    }
}

// ---------------------------------------------------------------------------
// Launcher (graph-capturable)
// ---------------------------------------------------------------------------
extern "C" void kernel_launch(void* const* d_in, const int* in_sizes, int n_in,
                              void* d_out, int out_size)
{
    const float* x      = (const float*)d_in[0];
    const float* w_attn = (const float*)d_in[1];
    const float* w_proj = (const float*)d_in[2];
    float* out = (float*)d_out;

    float *qkv_p = nullptr, *y_p = nullptr, *rope_p = nullptr;
    cudaGetSymbolAddress((void**)&qkv_p, g_qkv);
    cudaGetSymbolAddress((void**)&y_p, g_y);
    cudaGetSymbolAddress((void**)&rope_p, g_rope);

    const int GEMM_SMEM = 4 * 128 * 40 * (int)sizeof(__nv_bfloat16);  // 40960 B
    cudaFuncSetAttribute(gemm_bf16x3_nt, cudaFuncAttributeMaxDynamicSharedMemorySize, GEMM_SMEM);

    // 0) rope table
    rope_table_kernel<<<(Tv * 32 + 255) / 256, 256>>>(rope_p);

    // 1) qkv = x @ w_attn^T   [8192,3072]
    gemm_bf16x3_nt<<<dim3(QKV_N / 128, Mv / 128), 256, GEMM_SMEM>>>(x, w_attn, qkv_p, Mv, QKV_N, Cv);

    // 2) RMSNorm + RoPE on q,k (in place)
    norm_rope_kernel<<<Mv, 512>>>(qkv_p, rope_p);

    // 3) Causal flash attention (3xBF16 tensor cores) -> g_y
    const int FLASH_SMEM = 8 * 64 * 72 * 2 + 2 * 64 * 68 * 4;  // 108544 B
    cudaFuncSetAttribute(flash_bf16_kernel, cudaFuncAttributeMaxDynamicSharedMemorySize, FLASH_SMEM);
    flash_bf16_kernel<<<dim3(Tv / 64, Bv * Hv), 256, FLASH_SMEM>>>(qkv_p, y_p);

    // 4) out = y @ w_proj^T   [8192,1024]
    gemm_bf16x3_nt<<<dim3(Cv / 128, Mv / 128), 256, GEMM_SMEM>>>(y_p, w_proj, out, Mv, Cv, Cv);
}

// round 9
// speedup vs baseline: 3.4432x; 1.2359x over previous
#include <cuda_runtime.h>
#include <cuda_bf16.h>
#include <math.h>
#include <mma.h>

using namespace nvcuda;

#define Bv 4
#define Tv 2048
#define Cv 1024
#define Hv 16
#define HDv 64
#define Mv (Bv * Tv)
#define QKV_N (3 * Cv)

__device__ float g_qkv[Mv * QKV_N];
__device__ float g_y[Mv * Cv];
__device__ float g_rope[2 * Tv * 32];

// ---------------------------------------------------------------------------
__global__ void rope_table_kernel(float* __restrict__ rope)
{
    int idx = blockIdx.x * blockDim.x + threadIdx.x;
    if (idx >= Tv * 32) return;
    int t = idx >> 5;
    int i = idx & 31;
    double inv_freq_d = exp(-(double)i * (9.210340371976184 / 32.0));
    float inv_freq = (float)inv_freq_d;
    float ang = (float)t * inv_freq;
    float cf = (float)cos((double)ang);
    float sf = (float)sin((double)ang);
    rope[idx] = __bfloat162float(__float2bfloat16(cf));
    rope[Tv * 32 + idx] = __bfloat162float(__float2bfloat16(sf));
}

// ---------------------------------------------------------------------------
__device__ __forceinline__ void bsplit4(const float4 v,
                                        __nv_bfloat16* __restrict__ h,
                                        __nv_bfloat16* __restrict__ l)
{
    __nv_bfloat16 hx = __float2bfloat16(v.x);
    __nv_bfloat16 hy = __float2bfloat16(v.y);
    __nv_bfloat16 hz = __float2bfloat16(v.z);
    __nv_bfloat16 hw = __float2bfloat16(v.w);
    h[0] = hx; h[1] = hy; h[2] = hz; h[3] = hw;
    l[0] = __float2bfloat16(v.x - __bfloat162float(hx));
    l[1] = __float2bfloat16(v.y - __bfloat162float(hy));
    l[2] = __float2bfloat16(v.z - __bfloat162float(hz));
    l[3] = __float2bfloat16(v.w - __bfloat162float(hw));
}

__device__ __forceinline__ void bpack4(const float4 v, uint2& h, uint2& l)
{
    __nv_bfloat162 h0 = __floats2bfloat162_rn(v.x, v.y);
    __nv_bfloat162 h1 = __floats2bfloat162_rn(v.z, v.w);
    __nv_bfloat162 l0 = __floats2bfloat162_rn(v.x - __bfloat162float(h0.x),
                                              v.y - __bfloat162float(h0.y));
    __nv_bfloat162 l1 = __floats2bfloat162_rn(v.z - __bfloat162float(h1.x),
                                              v.w - __bfloat162float(h1.y));
    h.x = *(unsigned*)&h0; h.y = *(unsigned*)&h1;
    l.x = *(unsigned*)&l0; l.y = *(unsigned*)&l1;
}

__device__ __forceinline__ void packsplit(float a, float b, unsigned& h, unsigned& l)
{
    __nv_bfloat16 ha = __float2bfloat16(a);
    __nv_bfloat16 hb = __float2bfloat16(b);
    __nv_bfloat162 hh;
    hh.x = ha; hh.y = hb;
    __nv_bfloat162 ll;
    ll.x = __float2bfloat16(a - __bfloat162float(ha));
    ll.y = __float2bfloat16(b - __bfloat162float(hb));
    h = *(unsigned*)&hh;
    l = *(unsigned*)&ll;
}

// ---------------------------------------------------------------------------
__device__ __forceinline__ void ldsm4(unsigned addr, unsigned* r)
{
    asm volatile("ldmatrix.sync.aligned.m8n8.x4.shared.b16 { %0, %1, %2, %3 }, [ %4 ];"
                 : "=r"(r[0]), "=r"(r[1]), "=r"(r[2]), "=r"(r[3]) : "r"(addr));
}
__device__ __forceinline__ void ldsm4t(unsigned addr, unsigned* r)
{
    asm volatile("ldmatrix.sync.aligned.m8n8.x4.trans.shared.b16 { %0, %1, %2, %3 }, [ %4 ];"
                 : "=r"(r[0]), "=r"(r[1]), "=r"(r[2]), "=r"(r[3]) : "r"(addr));
}
__device__ __forceinline__ void mma_bf16(float* c, const unsigned* a,
                                         unsigned b0, unsigned b1)
{
    asm volatile("mma.sync.aligned.m16n8k16.row.col.f32.bf16.bf16.f32 "
                 "{ %0, %1, %2, %3 }, { %4, %5, %6, %7 }, { %8, %9 }, { %0, %1, %2, %3 };"
                 : "+f"(c[0]), "+f"(c[1]), "+f"(c[2]), "+f"(c[3])
                 : "r"(a[0]), "r"(a[1]), "r"(a[2]), "r"(a[3]), "r"(b0), "r"(b1));
}

// ---------------------------------------------------------------------------
// GEMM (NT), 3xBF16 (unchanged from round 6)
// ---------------------------------------------------------------------------
__global__ void __launch_bounds__(256) gemm_bf16x3_nt(
    const float* __restrict__ A, const float* __restrict__ B,
    float* __restrict__ C, int M, int N, int K)
{
    constexpr int BM = 128, BN = 128, BK = 32, LD = 40;
    extern __shared__ __align__(16) char smraw[];
    __nv_bfloat16* Ah = (__nv_bfloat16*)smraw;
    __nv_bfloat16* Al = Ah + BM * LD;
    __nv_bfloat16* Bh = Al + BM * LD;
    __nv_bfloat16* Bl = Bh + BN * LD;

    const int tid = threadIdx.x;
    const int m0 = blockIdx.y * BM;
    const int n0 = blockIdx.x * BN;
    const int w = tid >> 5;
    const int wm = w >> 1;
    const int wn = w & 1;

    wmma::fragment<wmma::accumulator, 16, 16, 16, float> acc[2][4];
#pragma unroll
    for (int i = 0; i < 2; i++)
#pragma unroll
        for (int j = 0; j < 4; j++)
            wmma::fill_fragment(acc[i][j], 0.0f);

    for (int k0 = 0; k0 < K; k0 += BK) {
#pragma unroll
        for (int idx = tid; idx < BM * BK / 4; idx += 256) {
            int r = idx >> 3;
            int c4 = (idx & 7) * 4;
            float4 v = *(const float4*)&A[(size_t)(m0 + r) * K + k0 + c4];
            bsplit4(v, &Ah[r * LD + c4], &Al[r * LD + c4]);
        }
#pragma unroll
        for (int idx = tid; idx < BN * BK / 4; idx += 256) {
            int r = idx >> 3;
            int c4 = (idx & 7) * 4;
            float4 v = *(const float4*)&B[(size_t)(n0 + r) * K + k0 + c4];
            bsplit4(v, &Bh[r * LD + c4], &Bl[r * LD + c4]);
        }
        __syncthreads();

#pragma unroll
        for (int kk = 0; kk < BK; kk += 16) {
            wmma::fragment<wmma::matrix_a, 16, 16, 16, __nv_bfloat16, wmma::row_major> afh[2];
            wmma::fragment<wmma::matrix_a, 16, 16, 16, __nv_bfloat16, wmma::row_major> afl[2];
            wmma::fragment<wmma::matrix_b, 16, 16, 16, __nv_bfloat16, wmma::col_major> bfh[4];
            wmma::fragment<wmma::matrix_b, 16, 16, 16, __nv_bfloat16, wmma::col_major> bfl[4];
#pragma unroll
            for (int i = 0; i < 2; i++) {
                wmma::load_matrix_sync(afh[i], &Ah[(wm * 32 + i * 16) * LD + kk], LD);
                wmma::load_matrix_sync(afl[i], &Al[(wm * 32 + i * 16) * LD + kk], LD);
            }
#pragma unroll
            for (int j = 0; j < 4; j++) {
                wmma::load_matrix_sync(bfh[j], &Bh[(wn * 64 + j * 16) * LD + kk], LD);
                wmma::load_matrix_sync(bfl[j], &Bl[(wn * 64 + j * 16) * LD + kk], LD);
            }
#pragma unroll
            for (int i = 0; i < 2; i++)
#pragma unroll
                for (int j = 0; j < 4; j++) {
                    wmma::mma_sync(acc[i][j], afh[i], bfl[j], acc[i][j]);
                    wmma::mma_sync(acc[i][j], afl[i], bfh[j], acc[i][j]);
                    wmma::mma_sync(acc[i][j], afh[i], bfh[j], acc[i][j]);
                }
        }
        __syncthreads();
    }

#pragma unroll
    for (int i = 0; i < 2; i++)
#pragma unroll
        for (int j = 0; j < 4; j++)
            wmma::store_matrix_sync(
                C + (size_t)(m0 + wm * 32 + i * 16) * N + n0 + wn * 64 + j * 16,
                acc[i][j], N, wmma::mem_row_major);
}

// ---------------------------------------------------------------------------
__global__ void __launch_bounds__(512) norm_rope_kernel(
    float* __restrict__ qkv, const float* __restrict__ rope)
{
    const int bt = blockIdx.x;
    const int t = bt & (Tv - 1);
    const int warp = threadIdx.x >> 5;
    const int lane = threadIdx.x & 31;

    float* qp = qkv + (size_t)bt * QKV_N + warp * HDv;
    float c = rope[t * 32 + lane];
    float s = rope[Tv * 32 + t * 32 + lane];

#pragma unroll
    for (int p = 0; p < 2; p++) {
        float* ptr = qp + p * Cv;
        float x1 = ptr[lane];
        float x2 = ptr[lane + 32];
        float ss = x1 * x1 + x2 * x2;
#pragma unroll
        for (int off = 16; off; off >>= 1)
            ss += __shfl_xor_sync(0xffffffffu, ss, off);
        float r = rsqrtf(ss * (1.0f / 64.0f) + 1.1920929e-07f);
        x1 *= r;
        x2 *= r;
        ptr[lane] = x1 * c + x2 * s;
        ptr[lane + 32] = -x1 * s + x2 * c;
    }
}

// ---------------------------------------------------------------------------
// Flash attention, raw mma.m16n8k16 (3xBF16), causal, online softmax.
// Q tile 128 rows, KV tile 64. 8 warps; warp owns rows [w*16, w*16+16).
// S/O register-resident; S D-frags become P A-frags directly.
// ---------------------------------------------------------------------------
__global__ void __launch_bounds__(256) flash_mma_kernel(
    const float* __restrict__ qkv, float* __restrict__ y)
{
    constexpr int LDB = 72;
    extern __shared__ __align__(16) char smraw[];
    __nv_bfloat16* Qh = (__nv_bfloat16*)smraw;
    __nv_bfloat16* Ql = Qh + 128 * LDB;
    __nv_bfloat16* Kh = Ql + 128 * LDB;
    __nv_bfloat16* Kl = Kh + 64 * LDB;
    __nv_bfloat16* Vh = Kl + 64 * LDB;
    __nv_bfloat16* Vl = Vh + 64 * LDB;

    const int qt = gridDim.x - 1 - blockIdx.x;
    const int bh = blockIdx.y;
    const int b = bh / Hv;
    const int h = bh % Hv;
    const int tid = threadIdx.x;
    const int wid = tid >> 5;
    const int lane = tid & 31;
    const int gid = lane >> 2;
    const int tig = lane & 3;

    const size_t rowbase = (size_t)b * Tv;
    const int q0 = qt * 128;

    const int arow = (lane & 7) + 8 * ((lane >> 3) & 1);
    const int acolo = 8 * (lane >> 4);
    const int brow = (lane & 7) + 8 * (lane >> 4);
    const int bcolo = 8 * ((lane >> 3) & 1);

    const unsigned QhS = (unsigned)__cvta_generic_to_shared(Qh);
    const unsigned QlS = (unsigned)__cvta_generic_to_shared(Ql);
    const unsigned KhS = (unsigned)__cvta_generic_to_shared(Kh);
    const unsigned KlS = (unsigned)__cvta_generic_to_shared(Kl);
    const unsigned VhS = (unsigned)__cvta_generic_to_shared(Vh);
    const unsigned VlS = (unsigned)__cvta_generic_to_shared(Vl);

    // function-scope temporaries (single declarator per line)
    float sc[8][4];
    float oc[8][4];
    unsigned qa[4];
    unsigned qb[4];
    unsigned ka[4];
    unsigned kb[4];
    unsigned va[4];
    unsigned vb[4];
    unsigned pah[4][4];
    unsigned pal[4][4];
    float mrow[2];
    float lrow[2];

    for (int idx = tid; idx < 128 * 16; idx += 256) {
        int r = idx >> 4;
        int c4 = (idx & 15) * 4;
        float4 v = *(const float4*)&qkv[(rowbase + q0 + r) * (size_t)QKV_N + h * HDv + c4];
        uint2 hp;
        uint2 lp;
        bpack4(v, hp, lp);
        *(uint2*)&Qh[r * LDB + c4] = hp;
        *(uint2*)&Ql[r * LDB + c4] = lp;
    }
    __syncthreads();

#pragma unroll
    for (int j = 0; j < 8; j++)
#pragma unroll
        for (int k = 0; k < 4; k++) oc[j][k] = 0.0f;

    mrow[0] = -1e30f;
    mrow[1] = -1e30f;
    lrow[0] = 0.0f;
    lrow[1] = 0.0f;
    const int r0g = q0 + wid * 16 + gid;
    const int r1g = r0g + 8;

    const int jt_max = 2 * qt + 1;
    for (int jt = 0; jt <= jt_max; jt++) {
        __syncthreads();
        for (int idx = tid; idx < 64 * 16; idx += 256) {
            int r = idx >> 4;
            int c4 = (idx & 15) * 4;
            size_t roff = (rowbase + jt * 64 + r) * (size_t)QKV_N + h * HDv + c4;
            float4 kv = *(const float4*)(qkv + roff + Cv);
            float4 vv = *(const float4*)(qkv + roff + 2 * Cv);
            uint2 hp;
            uint2 lp;
            bpack4(kv, hp, lp);
            *(uint2*)&Kh[r * LDB + c4] = hp;
            *(uint2*)&Kl[r * LDB + c4] = lp;
            bpack4(vv, hp, lp);
            *(uint2*)&Vh[r * LDB + c4] = hp;
            *(uint2*)&Vl[r * LDB + c4] = lp;
        }
        __syncthreads();

        // ---- S = Q K^T ----
#pragma unroll
        for (int j = 0; j < 8; j++)
#pragma unroll
            for (int k = 0; k < 4; k++) sc[j][k] = 0.0f;

#pragma unroll
        for (int t = 0; t < 4; t++) {
            unsigned qoff = (unsigned)(((wid * 16 + arow) * LDB + t * 16 + acolo) * 2);
            ldsm4(QhS + qoff, qa);
            ldsm4(QlS + qoff, qb);
#pragma unroll
            for (int g = 0; g < 4; g++) {
                unsigned koff = (unsigned)(((g * 16 + brow) * LDB + t * 16 + bcolo) * 2);
                ldsm4(KhS + koff, ka);
                ldsm4(KlS + koff, kb);
                mma_bf16(sc[2 * g], qa, kb[0], kb[1]);
                mma_bf16(sc[2 * g], qb, ka[0], ka[1]);
                mma_bf16(sc[2 * g], qa, ka[0], ka[1]);
                mma_bf16(sc[2 * g + 1], qa, kb[2], kb[3]);
                mma_bf16(sc[2 * g + 1], qb, ka[2], ka[3]);
                mma_bf16(sc[2 * g + 1], qa, ka[2], ka[3]);
            }
        }

        // ---- softmax in registers ----
        const bool maskp = (jt >= 2 * qt);
        float mt0 = -1e30f;
        float mt1 = -1e30f;
#pragma unroll
        for (int j = 0; j < 8; j++) {
            int c0 = jt * 64 + j * 8 + tig * 2;
            sc[j][0] *= 0.125f;
            sc[j][1] *= 0.125f;
            sc[j][2] *= 0.125f;
            sc[j][3] *= 0.125f;
            if (maskp) {
                if (c0 > r0g) sc[j][0] = -1e30f;
                if (c0 + 1 > r0g) sc[j][1] = -1e30f;
                if (c0 > r1g) sc[j][2] = -1e30f;
                if (c0 + 1 > r1g) sc[j][3] = -1e30f;
            }
            mt0 = fmaxf(mt0, fmaxf(sc[j][0], sc[j][1]));
            mt1 = fmaxf(mt1, fmaxf(sc[j][2], sc[j][3]));
        }
        mt0 = fmaxf(mt0, __shfl_xor_sync(0xffffffffu, mt0, 1));
        mt0 = fmaxf(mt0, __shfl_xor_sync(0xffffffffu, mt0, 2));
        mt1 = fmaxf(mt1, __shfl_xor_sync(0xffffffffu, mt1, 1));
        mt1 = fmaxf(mt1, __shfl_xor_sync(0xffffffffu, mt1, 2));

        float mn0 = fmaxf(mrow[0], mt0);
        float mn1 = fmaxf(mrow[1], mt1);
        float corr0 = expf(mrow[0] - mn0);
        float corr1 = expf(mrow[1] - mn1);

        float s0 = 0.0f;
        float s1 = 0.0f;
#pragma unroll
        for (int t = 0; t < 4; t++) {
            float p00 = expf(sc[2 * t][0] - mn0);
            float p01 = expf(sc[2 * t][1] - mn0);
            float p02 = expf(sc[2 * t][2] - mn1);
            float p03 = expf(sc[2 * t][3] - mn1);
            float p10 = expf(sc[2 * t + 1][0] - mn0);
            float p11 = expf(sc[2 * t + 1][1] - mn0);
            float p12 = expf(sc[2 * t + 1][2] - mn1);
            float p13 = expf(sc[2 * t + 1][3] - mn1);
            s0 += p00 + p01 + p10 + p11;
            s1 += p02 + p03 + p12 + p13;
            packsplit(p00, p01, pah[t][0], pal[t][0]);
            packsplit(p02, p03, pah[t][1], pal[t][1]);
            packsplit(p10, p11, pah[t][2], pal[t][2]);
            packsplit(p12, p13, pah[t][3], pal[t][3]);
        }
        s0 += __shfl_xor_sync(0xffffffffu, s0, 1);
        s0 += __shfl_xor_sync(0xffffffffu, s0, 2);
        s1 += __shfl_xor_sync(0xffffffffu, s1, 1);
        s1 += __shfl_xor_sync(0xffffffffu, s1, 2);

        lrow[0] = lrow[0] * corr0 + s0;
        lrow[1] = lrow[1] * corr1 + s1;
        mrow[0] = mn0;
        mrow[1] = mn1;
#pragma unroll
        for (int j = 0; j < 8; j++) {
            oc[j][0] *= corr0;
            oc[j][1] *= corr0;
            oc[j][2] *= corr1;
            oc[j][3] *= corr1;
        }

        // ---- O += P V ----
#pragma unroll
        for (int t = 0; t < 4; t++) {
#pragma unroll
            for (int n = 0; n < 4; n++) {
                unsigned voff = (unsigned)(((t * 16 + arow) * LDB + n * 16 + acolo) * 2);
                ldsm4t(VhS + voff, va);
                ldsm4t(VlS + voff, vb);
                mma_bf16(oc[2 * n], pah[t], vb[0], vb[1]);
                mma_bf16(oc[2 * n], pal[t], va[0], va[1]);
                mma_bf16(oc[2 * n], pah[t], va[0], va[1]);
                mma_bf16(oc[2 * n + 1], pah[t], vb[2], vb[3]);
                mma_bf16(oc[2 * n + 1], pal[t], va[2], va[3]);
                mma_bf16(oc[2 * n + 1], pah[t], va[2], va[3]);
            }
        }
    }

    float i0 = 1.0f / lrow[0];
    float i1 = 1.0f / lrow[1];
#pragma unroll
    for (int j = 0; j < 8; j++) {
        int col = h * HDv + j * 8 + tig * 2;
        *(float2*)&y[(rowbase + r0g) * (size_t)Cv + col] =
            make_float2(oc[j][0] * i0, oc[j][1] * i0);
        *(float2*)&y[(rowbase + r1g) * (size_t)Cv + col] =
            make_float2(oc[j][2] * i1, oc[j][3] * i1);
    }
}

// ---------------------------------------------------------------------------
extern "C" void kernel_launch(void* const* d_in, const int* in_sizes, int n_in,
                              void* d_out, int out_size)
{
    const float* x = (const float*)d_in[0];
    const float* w_attn = (const float*)d_in[1];
    const float* w_proj = (const float*)d_in[2];
    float* out = (float*)d_out;

    float* qkv_p = nullptr;
    float* y_p = nullptr;
    float* rope_p = nullptr;
    cudaGetSymbolAddress((void**)&qkv_p, g_qkv);
    cudaGetSymbolAddress((void**)&y_p, g_y);
    cudaGetSymbolAddress((void**)&rope_p, g_rope);

    const int GEMM_SMEM = 4 * 128 * 40 * (int)sizeof(__nv_bfloat16);  // 40960 B
    cudaFuncSetAttribute(gemm_bf16x3_nt, cudaFuncAttributeMaxDynamicSharedMemorySize, GEMM_SMEM);

    rope_table_kernel<<<(Tv * 32 + 255) / 256, 256>>>(rope_p);

    gemm_bf16x3_nt<<<dim3(QKV_N / 128, Mv / 128), 256, GEMM_SMEM>>>(x, w_attn, qkv_p, Mv, QKV_N, Cv);

    norm_rope_kernel<<<Mv, 512>>>(qkv_p, rope_p);

    const int FLASH_SMEM = (2 * 128 * 72 + 4 * 64 * 72) * (int)sizeof(__nv_bfloat16);  // 73728 B
    cudaFuncSetAttribute(flash_mma_kernel, cudaFuncAttributeMaxDynamicSharedMemorySize, FLASH_SMEM);
    flash_mma_kernel<<<dim3(Tv / 128, Bv * Hv), 256, FLASH_SMEM>>>(qkv_p, y_p);

    gemm_bf16x3_nt<<<dim3(Cv / 128, Mv / 128), 256, GEMM_SMEM>>>(y_p, w_proj, out, Mv, Cv, Cv);
}

// round 10
// speedup vs baseline: 4.4139x; 1.2819x over previous
#include <cuda_runtime.h>
#include <cuda_bf16.h>
#include <math.h>
#include <mma.h>

using namespace nvcuda;

#define Bv 4
#define Tv 2048
#define Cv 1024
#define Hv 16
#define HDv 64
#define Mv (Bv * Tv)
#define QKV_N (3 * Cv)

__device__ float g_qkv[Mv * QKV_N];
__device__ float g_y[Mv * Cv];
__device__ float g_rope[2 * Tv * 32];
// pre-split bf16 operands
__device__ __nv_bfloat16 g_ah[Mv * Cv];       // x, later y (hi)
__device__ __nv_bfloat16 g_al[Mv * Cv];       // x, later y (lo)
__device__ __nv_bfloat16 g_wh[4 * Cv * Cv];   // w_attn (3M) + w_proj (1M) hi
__device__ __nv_bfloat16 g_wl[4 * Cv * Cv];   // lo

// ---------------------------------------------------------------------------
__global__ void rope_table_kernel(float* __restrict__ rope)
{
    int idx = blockIdx.x * blockDim.x + threadIdx.x;
    if (idx >= Tv * 32) return;
    int t = idx >> 5;
    int i = idx & 31;
    double inv_freq_d = exp(-(double)i * (9.210340371976184 / 32.0));
    float inv_freq = (float)inv_freq_d;
    float ang = (float)t * inv_freq;
    float cf = (float)cos((double)ang);
    float sf = (float)sin((double)ang);
    rope[idx] = __bfloat162float(__float2bfloat16(cf));
    rope[Tv * 32 + idx] = __bfloat162float(__float2bfloat16(sf));
}

// ---------------------------------------------------------------------------
__device__ __forceinline__ void bpack4(const float4 v, uint2& h, uint2& l)
{
    __nv_bfloat162 h0 = __floats2bfloat162_rn(v.x, v.y);
    __nv_bfloat162 h1 = __floats2bfloat162_rn(v.z, v.w);
    __nv_bfloat162 l0 = __floats2bfloat162_rn(v.x - __bfloat162float(h0.x),
                                              v.y - __bfloat162float(h0.y));
    __nv_bfloat162 l1 = __floats2bfloat162_rn(v.z - __bfloat162float(h1.x),
                                              v.w - __bfloat162float(h1.y));
    h.x = *(unsigned*)&h0; h.y = *(unsigned*)&h1;
    l.x = *(unsigned*)&l0; l.y = *(unsigned*)&l1;
}

__device__ __forceinline__ void packsplit(float a, float b, unsigned& h, unsigned& l)
{
    __nv_bfloat16 ha = __float2bfloat16(a);
    __nv_bfloat16 hb = __float2bfloat16(b);
    __nv_bfloat162 hh;
    hh.x = ha; hh.y = hb;
    __nv_bfloat162 ll;
    ll.x = __float2bfloat16(a - __bfloat162float(ha));
    ll.y = __float2bfloat16(b - __bfloat162float(hb));
    h = *(unsigned*)&hh;
    l = *(unsigned*)&ll;
}

// fp32 -> bf16 hi/lo pack (elementwise, 4 at a time)
__global__ void pack_split_kernel(const float* __restrict__ in,
                                  __nv_bfloat16* __restrict__ h,
                                  __nv_bfloat16* __restrict__ l, int n4)
{
    int i = blockIdx.x * blockDim.x + threadIdx.x;
    if (i >= n4) return;
    float4 v = ((const float4*)in)[i];
    uint2 hp;
    uint2 lp;
    bpack4(v, hp, lp);
    ((uint2*)h)[i] = hp;
    ((uint2*)l)[i] = lp;
}

// ---------------------------------------------------------------------------
__device__ __forceinline__ void ldsm4(unsigned addr, unsigned* r)
{
    asm volatile("ldmatrix.sync.aligned.m8n8.x4.shared.b16 { %0, %1, %2, %3 }, [ %4 ];"
                 : "=r"(r[0]), "=r"(r[1]), "=r"(r[2]), "=r"(r[3]) : "r"(addr));
}
__device__ __forceinline__ void ldsm4t(unsigned addr, unsigned* r)
{
    asm volatile("ldmatrix.sync.aligned.m8n8.x4.trans.shared.b16 { %0, %1, %2, %3 }, [ %4 ];"
                 : "=r"(r[0]), "=r"(r[1]), "=r"(r[2]), "=r"(r[3]) : "r"(addr));
}
__device__ __forceinline__ void mma_bf16(float* c, const unsigned* a,
                                         unsigned b0, unsigned b1)
{
    asm volatile("mma.sync.aligned.m16n8k16.row.col.f32.bf16.bf16.f32 "
                 "{ %0, %1, %2, %3 }, { %4, %5, %6, %7 }, { %8, %9 }, { %0, %1, %2, %3 };"
                 : "+f"(c[0]), "+f"(c[1]), "+f"(c[2]), "+f"(c[3])
                 : "r"(a[0]), "r"(a[1]), "r"(a[2]), "r"(a[3]), "r"(b0), "r"(b1));
}
__device__ __forceinline__ void cp16(unsigned dst, const void* src)
{
    asm volatile("cp.async.cg.shared.global [ %0 ], [ %1 ], 16;" :: "r"(dst), "l"(src));
}
__device__ __forceinline__ void cpcommit()
{
    asm volatile("cp.async.commit_group;");
}
__device__ __forceinline__ void cpwait0()
{
    asm volatile("cp.async.wait_group 0;");
}
__device__ __forceinline__ void cpwait1()
{
    asm volatile("cp.async.wait_group 1;");
}

// ---------------------------------------------------------------------------
// GEMM (NT): C[M,N] = (Ah+Al)[M,K] * (Bh+Bl)[N,K]^T, pre-split bf16 inputs,
// 3-term emulated fp32. cp.async 2-stage pipeline, BK=32, BM=BN=128.
// ---------------------------------------------------------------------------
__global__ void __launch_bounds__(256) gemm_bf16_pre(
    const __nv_bfloat16* __restrict__ Ah, const __nv_bfloat16* __restrict__ Al,
    const __nv_bfloat16* __restrict__ Bh, const __nv_bfloat16* __restrict__ Bl,
    float* __restrict__ C, int M, int N, int K)
{
    constexpr int BM = 128, BN = 128, BK = 32, LD = 40;
    constexpr int STG = 4 * 128 * LD;   // bf16 elems per stage
    extern __shared__ __align__(16) char smraw[];
    __nv_bfloat16* sm = (__nv_bfloat16*)smraw;
    const unsigned smS = (unsigned)__cvta_generic_to_shared(sm);

    const int tid = threadIdx.x;
    const int m0 = blockIdx.y * BM;
    const int n0 = blockIdx.x * BN;
    const int w = tid >> 5;
    const int wm = w >> 1;
    const int wn = w & 1;

    wmma::fragment<wmma::accumulator, 16, 16, 16, float> acc[2][4];
#pragma unroll
    for (int i = 0; i < 2; i++)
#pragma unroll
        for (int j = 0; j < 4; j++)
            wmma::fill_fragment(acc[i][j], 0.0f);

    const int nk = K / BK;

    // stage loader: 4 arrays x 512 16B-chunks (chunk = 8 bf16)
    const __nv_bfloat16* srcs[4];
    srcs[0] = Ah; srcs[1] = Al; srcs[2] = Bh; srcs[3] = Bl;

#define LOAD_STAGE(stg, k0)                                                   \
    do {                                                                      \
        unsigned sb = smS + (unsigned)((stg) * STG * 2);                      \
        for (int arr = 0; arr < 4; arr++) {                                   \
            int g0 = (arr < 2) ? m0 : n0;                                     \
            const __nv_bfloat16* sp = srcs[arr];                              \
            for (int c = tid; c < 512; c += 256) {                            \
                int r = c >> 2;                                               \
                int coff = (c & 3) * 8;                                       \
                unsigned dst = sb + (unsigned)((arr * 128 * LD + r * LD + coff) * 2); \
                cp16(dst, sp + (size_t)(g0 + r) * K + (k0) + coff);           \
            }                                                                 \
        }                                                                     \
    } while (0)

    LOAD_STAGE(0, 0);
    cpcommit();

    for (int kt = 0; kt < nk; kt++) {
        if (kt + 1 < nk) {
            LOAD_STAGE((kt + 1) & 1, (kt + 1) * BK);
            cpcommit();
            cpwait1();
        } else {
            cpwait0();
        }
        __syncthreads();

        __nv_bfloat16* sAh = sm + (kt & 1) * STG;
        __nv_bfloat16* sAl = sAh + 128 * LD;
        __nv_bfloat16* sBh = sAl + 128 * LD;
        __nv_bfloat16* sBl = sBh + 128 * LD;

#pragma unroll
        for (int kk = 0; kk < BK; kk += 16) {
            wmma::fragment<wmma::matrix_a, 16, 16, 16, __nv_bfloat16, wmma::row_major> afh[2];
            wmma::fragment<wmma::matrix_a, 16, 16, 16, __nv_bfloat16, wmma::row_major> afl[2];
            wmma::fragment<wmma::matrix_b, 16, 16, 16, __nv_bfloat16, wmma::col_major> bfh[4];
            wmma::fragment<wmma::matrix_b, 16, 16, 16, __nv_bfloat16, wmma::col_major> bfl[4];
#pragma unroll
            for (int i = 0; i < 2; i++) {
                wmma::load_matrix_sync(afh[i], &sAh[(wm * 32 + i * 16) * LD + kk], LD);
                wmma::load_matrix_sync(afl[i], &sAl[(wm * 32 + i * 16) * LD + kk], LD);
            }
#pragma unroll
            for (int j = 0; j < 4; j++) {
                wmma::load_matrix_sync(bfh[j], &sBh[(wn * 64 + j * 16) * LD + kk], LD);
                wmma::load_matrix_sync(bfl[j], &sBl[(wn * 64 + j * 16) * LD + kk], LD);
            }
#pragma unroll
            for (int i = 0; i < 2; i++)
#pragma unroll
                for (int j = 0; j < 4; j++) {
                    wmma::mma_sync(acc[i][j], afh[i], bfl[j], acc[i][j]);
                    wmma::mma_sync(acc[i][j], afl[i], bfh[j], acc[i][j]);
                    wmma::mma_sync(acc[i][j], afh[i], bfh[j], acc[i][j]);
                }
        }
        __syncthreads();
    }
#undef LOAD_STAGE

#pragma unroll
    for (int i = 0; i < 2; i++)
#pragma unroll
        for (int j = 0; j < 4; j++)
            wmma::store_matrix_sync(
                C + (size_t)(m0 + wm * 32 + i * 16) * N + n0 + wn * 64 + j * 16,
                acc[i][j], N, wmma::mem_row_major);
}

// ---------------------------------------------------------------------------
__global__ void __launch_bounds__(512) norm_rope_kernel(
    float* __restrict__ qkv, const float* __restrict__ rope)
{
    const int bt = blockIdx.x;
    const int t = bt & (Tv - 1);
    const int warp = threadIdx.x >> 5;
    const int lane = threadIdx.x & 31;

    float* qp = qkv + (size_t)bt * QKV_N + warp * HDv;
    float c = rope[t * 32 + lane];
    float s = rope[Tv * 32 + t * 32 + lane];

#pragma unroll
    for (int p = 0; p < 2; p++) {
        float* ptr = qp + p * Cv;
        float x1 = ptr[lane];
        float x2 = ptr[lane + 32];
        float ss = x1 * x1 + x2 * x2;
#pragma unroll
        for (int off = 16; off; off >>= 1)
            ss += __shfl_xor_sync(0xffffffffu, ss, off);
        float r = rsqrtf(ss * (1.0f / 64.0f) + 1.1920929e-07f);
        x1 *= r;
        x2 *= r;
        ptr[lane] = x1 * c + x2 * s;
        ptr[lane + 32] = -x1 * s + x2 * c;
    }
}

// ---------------------------------------------------------------------------
// Flash attention (unchanged from round 9: raw mma, register S/O, 3xBF16)
// ---------------------------------------------------------------------------
__global__ void __launch_bounds__(256) flash_mma_kernel(
    const float* __restrict__ qkv, float* __restrict__ y)
{
    constexpr int LDB = 72;
    extern __shared__ __align__(16) char smraw[];
    __nv_bfloat16* Qh = (__nv_bfloat16*)smraw;
    __nv_bfloat16* Ql = Qh + 128 * LDB;
    __nv_bfloat16* Kh = Ql + 128 * LDB;
    __nv_bfloat16* Kl = Kh + 64 * LDB;
    __nv_bfloat16* Vh = Kl + 64 * LDB;
    __nv_bfloat16* Vl = Vh + 64 * LDB;

    const int qt = gridDim.x - 1 - blockIdx.x;
    const int bh = blockIdx.y;
    const int b = bh / Hv;
    const int h = bh % Hv;
    const int tid = threadIdx.x;
    const int wid = tid >> 5;
    const int lane = tid & 31;
    const int gid = lane >> 2;
    const int tig = lane & 3;

    const size_t rowbase = (size_t)b * Tv;
    const int q0 = qt * 128;

    const int arow = (lane & 7) + 8 * ((lane >> 3) & 1);
    const int acolo = 8 * (lane >> 4);
    const int brow = (lane & 7) + 8 * (lane >> 4);
    const int bcolo = 8 * ((lane >> 3) & 1);

    const unsigned QhS = (unsigned)__cvta_generic_to_shared(Qh);
    const unsigned QlS = (unsigned)__cvta_generic_to_shared(Ql);
    const unsigned KhS = (unsigned)__cvta_generic_to_shared(Kh);
    const unsigned KlS = (unsigned)__cvta_generic_to_shared(Kl);
    const unsigned VhS = (unsigned)__cvta_generic_to_shared(Vh);
    const unsigned VlS = (unsigned)__cvta_generic_to_shared(Vl);

    float sc[8][4];
    float oc[8][4];
    unsigned qa[4];
    unsigned qb[4];
    unsigned ka[4];
    unsigned kb[4];
    unsigned va[4];
    unsigned vb[4];
    unsigned pah[4][4];
    unsigned pal[4][4];
    float mrow[2];
    float lrow[2];

    for (int idx = tid; idx < 128 * 16; idx += 256) {
        int r = idx >> 4;
        int c4 = (idx & 15) * 4;
        float4 v = *(const float4*)&qkv[(rowbase + q0 + r) * (size_t)QKV_N + h * HDv + c4];
        uint2 hp;
        uint2 lp;
        bpack4(v, hp, lp);
        *(uint2*)&Qh[r * LDB + c4] = hp;
        *(uint2*)&Ql[r * LDB + c4] = lp;
    }
    __syncthreads();

#pragma unroll
    for (int j = 0; j < 8; j++)
#pragma unroll
        for (int k = 0; k < 4; k++) oc[j][k] = 0.0f;

    mrow[0] = -1e30f;
    mrow[1] = -1e30f;
    lrow[0] = 0.0f;
    lrow[1] = 0.0f;
    const int r0g = q0 + wid * 16 + gid;
    const int r1g = r0g + 8;

    const int jt_max = 2 * qt + 1;
    for (int jt = 0; jt <= jt_max; jt++) {
        __syncthreads();
        for (int idx = tid; idx < 64 * 16; idx += 256) {
            int r = idx >> 4;
            int c4 = (idx & 15) * 4;
            size_t roff = (rowbase + jt * 64 + r) * (size_t)QKV_N + h * HDv + c4;
            float4 kv = *(const float4*)(qkv + roff + Cv);
            float4 vv = *(const float4*)(qkv + roff + 2 * Cv);
            uint2 hp;
            uint2 lp;
            bpack4(kv, hp, lp);
            *(uint2*)&Kh[r * LDB + c4] = hp;
            *(uint2*)&Kl[r * LDB + c4] = lp;
            bpack4(vv, hp, lp);
            *(uint2*)&Vh[r * LDB + c4] = hp;
            *(uint2*)&Vl[r * LDB + c4] = lp;
        }
        __syncthreads();

#pragma unroll
        for (int j = 0; j < 8; j++)
#pragma unroll
            for (int k = 0; k < 4; k++) sc[j][k] = 0.0f;

#pragma unroll
        for (int t = 0; t < 4; t++) {
            unsigned qoff = (unsigned)(((wid * 16 + arow) * LDB + t * 16 + acolo) * 2);
            ldsm4(QhS + qoff, qa);
            ldsm4(QlS + qoff, qb);
#pragma unroll
            for (int g = 0; g < 4; g++) {
                unsigned koff = (unsigned)(((g * 16 + brow) * LDB + t * 16 + bcolo) * 2);
                ldsm4(KhS + koff, ka);
                ldsm4(KlS + koff, kb);
                mma_bf16(sc[2 * g], qa, kb[0], kb[1]);
                mma_bf16(sc[2 * g], qb, ka[0], ka[1]);
                mma_bf16(sc[2 * g], qa, ka[0], ka[1]);
                mma_bf16(sc[2 * g + 1], qa, kb[2], kb[3]);
                mma_bf16(sc[2 * g + 1], qb, ka[2], ka[3]);
                mma_bf16(sc[2 * g + 1], qa, ka[2], ka[3]);
            }
        }

        const bool maskp = (jt >= 2 * qt);
        float mt0 = -1e30f;
        float mt1 = -1e30f;
#pragma unroll
        for (int j = 0; j < 8; j++) {
            int c0 = jt * 64 + j * 8 + tig * 2;
            sc[j][0] *= 0.125f;
            sc[j][1] *= 0.125f;
            sc[j][2] *= 0.125f;
            sc[j][3] *= 0.125f;
            if (maskp) {
                if (c0 > r0g) sc[j][0] = -1e30f;
                if (c0 + 1 > r0g) sc[j][1] = -1e30f;
                if (c0 > r1g) sc[j][2] = -1e30f;
                if (c0 + 1 > r1g) sc[j][3] = -1e30f;
            }
            mt0 = fmaxf(mt0, fmaxf(sc[j][0], sc[j][1]));
            mt1 = fmaxf(mt1, fmaxf(sc[j][2], sc[j][3]));
        }
        mt0 = fmaxf(mt0, __shfl_xor_sync(0xffffffffu, mt0, 1));
        mt0 = fmaxf(mt0, __shfl_xor_sync(0xffffffffu, mt0, 2));
        mt1 = fmaxf(mt1, __shfl_xor_sync(0xffffffffu, mt1, 1));
        mt1 = fmaxf(mt1, __shfl_xor_sync(0xffffffffu, mt1, 2));

        float mn0 = fmaxf(mrow[0], mt0);
        float mn1 = fmaxf(mrow[1], mt1);
        float corr0 = expf(mrow[0] - mn0);
        float corr1 = expf(mrow[1] - mn1);

        float s0 = 0.0f;
        float s1 = 0.0f;
#pragma unroll
        for (int t = 0; t < 4; t++) {
            float p00 = expf(sc[2 * t][0] - mn0);
            float p01 = expf(sc[2 * t][1] - mn0);
            float p02 = expf(sc[2 * t][2] - mn1);
            float p03 = expf(sc[2 * t][3] - mn1);
            float p10 = expf(sc[2 * t + 1][0] - mn0);
            float p11 = expf(sc[2 * t + 1][1] - mn0);
            float p12 = expf(sc[2 * t + 1][2] - mn1);
            float p13 = expf(sc[2 * t + 1][3] - mn1);
            s0 += p00 + p01 + p10 + p11;
            s1 += p02 + p03 + p12 + p13;
            packsplit(p00, p01, pah[t][0], pal[t][0]);
            packsplit(p02, p03, pah[t][1], pal[t][1]);
            packsplit(p10, p11, pah[t][2], pal[t][2]);
            packsplit(p12, p13, pah[t][3], pal[t][3]);
        }
        s0 += __shfl_xor_sync(0xffffffffu, s0, 1);
        s0 += __shfl_xor_sync(0xffffffffu, s0, 2);
        s1 += __shfl_xor_sync(0xffffffffu, s1, 1);
        s1 += __shfl_xor_sync(0xffffffffu, s1, 2);

        lrow[0] = lrow[0] * corr0 + s0;
        lrow[1] = lrow[1] * corr1 + s1;
        mrow[0] = mn0;
        mrow[1] = mn1;
#pragma unroll
        for (int j = 0; j < 8; j++) {
            oc[j][0] *= corr0;
            oc[j][1] *= corr0;
            oc[j][2] *= corr1;
            oc[j][3] *= corr1;
        }

#pragma unroll
        for (int t = 0; t < 4; t++) {
#pragma unroll
            for (int n = 0; n < 4; n++) {
                unsigned voff = (unsigned)(((t * 16 + arow) * LDB + n * 16 + acolo) * 2);
                ldsm4t(VhS + voff, va);
                ldsm4t(VlS + voff, vb);
                mma_bf16(oc[2 * n], pah[t], vb[0], vb[1]);
                mma_bf16(oc[2 * n], pal[t], va[0], va[1]);
                mma_bf16(oc[2 * n], pah[t], va[0], va[1]);
                mma_bf16(oc[2 * n + 1], pah[t], vb[2], vb[3]);
                mma_bf16(oc[2 * n + 1], pal[t], va[2], va[3]);
                mma_bf16(oc[2 * n + 1], pah[t], va[2], va[3]);
            }
        }
    }

    float i0 = 1.0f / lrow[0];
    float i1 = 1.0f / lrow[1];
#pragma unroll
    for (int j = 0; j < 8; j++) {
        int col = h * HDv + j * 8 + tig * 2;
        *(float2*)&y[(rowbase + r0g) * (size_t)Cv + col] =
            make_float2(oc[j][0] * i0, oc[j][1] * i0);
        *(float2*)&y[(rowbase + r1g) * (size_t)Cv + col] =
            make_float2(oc[j][2] * i1, oc[j][3] * i1);
    }
}

// ---------------------------------------------------------------------------
extern "C" void kernel_launch(void* const* d_in, const int* in_sizes, int n_in,
                              void* d_out, int out_size)
{
    const float* x = (const float*)d_in[0];
    const float* w_attn = (const float*)d_in[1];
    const float* w_proj = (const float*)d_in[2];
    float* out = (float*)d_out;

    float* qkv_p = nullptr;
    float* y_p = nullptr;
    float* rope_p = nullptr;
    __nv_bfloat16* ah_p = nullptr;
    __nv_bfloat16* al_p = nullptr;
    __nv_bfloat16* wh_p = nullptr;
    __nv_bfloat16* wl_p = nullptr;
    cudaGetSymbolAddress((void**)&qkv_p, g_qkv);
    cudaGetSymbolAddress((void**)&y_p, g_y);
    cudaGetSymbolAddress((void**)&rope_p, g_rope);
    cudaGetSymbolAddress((void**)&ah_p, g_ah);
    cudaGetSymbolAddress((void**)&al_p, g_al);
    cudaGetSymbolAddress((void**)&wh_p, g_wh);
    cudaGetSymbolAddress((void**)&wl_p, g_wl);

    const int GEMM_SMEM = 2 * 4 * 128 * 40 * (int)sizeof(__nv_bfloat16);  // 81920 B
    cudaFuncSetAttribute(gemm_bf16_pre, cudaFuncAttributeMaxDynamicSharedMemorySize, GEMM_SMEM);

    rope_table_kernel<<<(Tv * 32 + 255) / 256, 256>>>(rope_p);

    // pack x, w_attn, w_proj into bf16 hi/lo
    pack_split_kernel<<<(Mv * Cv / 4 + 255) / 256, 256>>>(x, ah_p, al_p, Mv * Cv / 4);
    pack_split_kernel<<<(QKV_N * Cv / 4 + 255) / 256, 256>>>(w_attn, wh_p, wl_p, QKV_N * Cv / 4);
    pack_split_kernel<<<(Cv * Cv / 4 + 255) / 256, 256>>>(
        w_proj, wh_p + QKV_N * Cv, wl_p + QKV_N * Cv, Cv * Cv / 4);

    // qkv = x @ w_attn^T
    gemm_bf16_pre<<<dim3(QKV_N / 128, Mv / 128), 256, GEMM_SMEM>>>(
        ah_p, al_p, wh_p, wl_p, qkv_p, Mv, QKV_N, Cv);

    norm_rope_kernel<<<Mv, 512>>>(qkv_p, rope_p);

    const int FLASH_SMEM = (2 * 128 * 72 + 4 * 64 * 72) * (int)sizeof(__nv_bfloat16);  // 73728 B
    cudaFuncSetAttribute(flash_mma_kernel, cudaFuncAttributeMaxDynamicSharedMemorySize, FLASH_SMEM);
    flash_mma_kernel<<<dim3(Tv / 128, Bv * Hv), 256, FLASH_SMEM>>>(qkv_p, y_p);

    // pack y, then out = y @ w_proj^T
    pack_split_kernel<<<(Mv * Cv / 4 + 255) / 256, 256>>>(y_p, ah_p, al_p, Mv * Cv / 4);
    gemm_bf16_pre<<<dim3(Cv / 128, Mv / 128), 256, GEMM_SMEM>>>(
        ah_p, al_p, wh_p + QKV_N * Cv, wl_p + QKV_N * Cv, out, Mv, Cv, Cv);
}

// round 11
// speedup vs baseline: 4.6252x; 1.0479x over previous
#include <cuda_runtime.h>
#include <cuda_bf16.h>
#include <math.h>
#include <mma.h>

using namespace nvcuda;

#define Bv 4
#define Tv 2048
#define Cv 1024
#define Hv 16
#define HDv 64
#define Mv (Bv * Tv)
#define QKV_N (3 * Cv)

__device__ float g_qkv[Mv * QKV_N];
__device__ float g_y[Mv * Cv];
__device__ float g_rope[2 * Tv * 32];
// pre-split bf16 operands for GEMMs
__device__ __nv_bfloat16 g_ah[Mv * Cv];
__device__ __nv_bfloat16 g_al[Mv * Cv];
__device__ __nv_bfloat16 g_wh[4 * Cv * Cv];
__device__ __nv_bfloat16 g_wl[4 * Cv * Cv];
// pre-split bf16 qkv (post norm+rope) for flash
__device__ __nv_bfloat16 g_qkvh[Mv * QKV_N];
__device__ __nv_bfloat16 g_qkvl[Mv * QKV_N];

// ---------------------------------------------------------------------------
__global__ void rope_table_kernel(float* __restrict__ rope)
{
    int idx = blockIdx.x * blockDim.x + threadIdx.x;
    if (idx >= Tv * 32) return;
    int t = idx >> 5;
    int i = idx & 31;
    double inv_freq_d = exp(-(double)i * (9.210340371976184 / 32.0));
    float inv_freq = (float)inv_freq_d;
    float ang = (float)t * inv_freq;
    float cf = (float)cos((double)ang);
    float sf = (float)sin((double)ang);
    rope[idx] = __bfloat162float(__float2bfloat16(cf));
    rope[Tv * 32 + idx] = __bfloat162float(__float2bfloat16(sf));
}

// ---------------------------------------------------------------------------
__device__ __forceinline__ void bpack4(const float4 v, uint2& h, uint2& l)
{
    __nv_bfloat162 h0 = __floats2bfloat162_rn(v.x, v.y);
    __nv_bfloat162 h1 = __floats2bfloat162_rn(v.z, v.w);
    __nv_bfloat162 l0 = __floats2bfloat162_rn(v.x - __bfloat162float(h0.x),
                                              v.y - __bfloat162float(h0.y));
    __nv_bfloat162 l1 = __floats2bfloat162_rn(v.z - __bfloat162float(h1.x),
                                              v.w - __bfloat162float(h1.y));
    h.x = *(unsigned*)&h0; h.y = *(unsigned*)&h1;
    l.x = *(unsigned*)&l0; l.y = *(unsigned*)&l1;
}

__device__ __forceinline__ void packsplit(float a, float b, unsigned& h, unsigned& l)
{
    __nv_bfloat16 ha = __float2bfloat16(a);
    __nv_bfloat16 hb = __float2bfloat16(b);
    __nv_bfloat162 hh;
    hh.x = ha; hh.y = hb;
    __nv_bfloat162 ll;
    ll.x = __float2bfloat16(a - __bfloat162float(ha));
    ll.y = __float2bfloat16(b - __bfloat162float(hb));
    h = *(unsigned*)&hh;
    l = *(unsigned*)&ll;
}

__device__ __forceinline__ void split1(float a,
                                       __nv_bfloat16* __restrict__ h,
                                       __nv_bfloat16* __restrict__ l)
{
    __nv_bfloat16 hi = __float2bfloat16(a);
    *h = hi;
    *l = __float2bfloat16(a - __bfloat162float(hi));
}

// fp32 -> bf16 hi/lo pack (elementwise, 4 at a time)
__global__ void pack_split_kernel(const float* __restrict__ in,
                                  __nv_bfloat16* __restrict__ h,
                                  __nv_bfloat16* __restrict__ l, int n4)
{
    int i = blockIdx.x * blockDim.x + threadIdx.x;
    if (i >= n4) return;
    float4 v = ((const float4*)in)[i];
    uint2 hp;
    uint2 lp;
    bpack4(v, hp, lp);
    ((uint2*)h)[i] = hp;
    ((uint2*)l)[i] = lp;
}

// ---------------------------------------------------------------------------
__device__ __forceinline__ void ldsm4(unsigned addr, unsigned* r)
{
    asm volatile("ldmatrix.sync.aligned.m8n8.x4.shared.b16 { %0, %1, %2, %3 }, [ %4 ];"
                 : "=r"(r[0]), "=r"(r[1]), "=r"(r[2]), "=r"(r[3]) : "r"(addr));
}
__device__ __forceinline__ void ldsm4t(unsigned addr, unsigned* r)
{
    asm volatile("ldmatrix.sync.aligned.m8n8.x4.trans.shared.b16 { %0, %1, %2, %3 }, [ %4 ];"
                 : "=r"(r[0]), "=r"(r[1]), "=r"(r[2]), "=r"(r[3]) : "r"(addr));
}
__device__ __forceinline__ void mma_bf16(float* c, const unsigned* a,
                                         unsigned b0, unsigned b1)
{
    asm volatile("mma.sync.aligned.m16n8k16.row.col.f32.bf16.bf16.f32 "
                 "{ %0, %1, %2, %3 }, { %4, %5, %6, %7 }, { %8, %9 }, { %0, %1, %2, %3 };"
                 : "+f"(c[0]), "+f"(c[1]), "+f"(c[2]), "+f"(c[3])
                 : "r"(a[0]), "r"(a[1]), "r"(a[2]), "r"(a[3]), "r"(b0), "r"(b1));
}
__device__ __forceinline__ void cp16(unsigned dst, const void* src)
{
    asm volatile("cp.async.cg.shared.global [ %0 ], [ %1 ], 16;" :: "r"(dst), "l"(src));
}
__device__ __forceinline__ void cpcommit()
{
    asm volatile("cp.async.commit_group;");
}
__device__ __forceinline__ void cpwait0()
{
    asm volatile("cp.async.wait_group 0;");
}
__device__ __forceinline__ void cpwait1()
{
    asm volatile("cp.async.wait_group 1;");
}

// ---------------------------------------------------------------------------
// GEMM (NT): 3-term emulated fp32, pre-split bf16, cp.async 2-stage (round 10)
// ---------------------------------------------------------------------------
__global__ void __launch_bounds__(256) gemm_bf16_pre(
    const __nv_bfloat16* __restrict__ Ah, const __nv_bfloat16* __restrict__ Al,
    const __nv_bfloat16* __restrict__ Bh, const __nv_bfloat16* __restrict__ Bl,
    float* __restrict__ C, int M, int N, int K)
{
    constexpr int BM = 128, BN = 128, BK = 32, LD = 40;
    constexpr int STG = 4 * 128 * LD;
    extern __shared__ __align__(16) char smraw[];
    __nv_bfloat16* sm = (__nv_bfloat16*)smraw;
    const unsigned smS = (unsigned)__cvta_generic_to_shared(sm);

    const int tid = threadIdx.x;
    const int m0 = blockIdx.y * BM;
    const int n0 = blockIdx.x * BN;
    const int w = tid >> 5;
    const int wm = w >> 1;
    const int wn = w & 1;

    wmma::fragment<wmma::accumulator, 16, 16, 16, float> acc[2][4];
#pragma unroll
    for (int i = 0; i < 2; i++)
#pragma unroll
        for (int j = 0; j < 4; j++)
            wmma::fill_fragment(acc[i][j], 0.0f);

    const int nk = K / BK;

    const __nv_bfloat16* srcs[4];
    srcs[0] = Ah; srcs[1] = Al; srcs[2] = Bh; srcs[3] = Bl;

#define LOAD_STAGE(stg, k0)                                                   \
    do {                                                                      \
        unsigned sb = smS + (unsigned)((stg) * STG * 2);                      \
        for (int arr = 0; arr < 4; arr++) {                                   \
            int g0 = (arr < 2) ? m0 : n0;                                     \
            const __nv_bfloat16* sp = srcs[arr];                              \
            for (int c = tid; c < 512; c += 256) {                            \
                int r = c >> 2;                                               \
                int coff = (c & 3) * 8;                                       \
                unsigned dst = sb + (unsigned)((arr * 128 * LD + r * LD + coff) * 2); \
                cp16(dst, sp + (size_t)(g0 + r) * K + (k0) + coff);           \
            }                                                                 \
        }                                                                     \
    } while (0)

    LOAD_STAGE(0, 0);
    cpcommit();

    for (int kt = 0; kt < nk; kt++) {
        if (kt + 1 < nk) {
            LOAD_STAGE((kt + 1) & 1, (kt + 1) * BK);
            cpcommit();
            cpwait1();
        } else {
            cpwait0();
        }
        __syncthreads();

        __nv_bfloat16* sAh = sm + (kt & 1) * STG;
        __nv_bfloat16* sAl = sAh + 128 * LD;
        __nv_bfloat16* sBh = sAl + 128 * LD;
        __nv_bfloat16* sBl = sBh + 128 * LD;

#pragma unroll
        for (int kk = 0; kk < BK; kk += 16) {
            wmma::fragment<wmma::matrix_a, 16, 16, 16, __nv_bfloat16, wmma::row_major> afh[2];
            wmma::fragment<wmma::matrix_a, 16, 16, 16, __nv_bfloat16, wmma::row_major> afl[2];
            wmma::fragment<wmma::matrix_b, 16, 16, 16, __nv_bfloat16, wmma::col_major> bfh[4];
            wmma::fragment<wmma::matrix_b, 16, 16, 16, __nv_bfloat16, wmma::col_major> bfl[4];
#pragma unroll
            for (int i = 0; i < 2; i++) {
                wmma::load_matrix_sync(afh[i], &sAh[(wm * 32 + i * 16) * LD + kk], LD);
                wmma::load_matrix_sync(afl[i], &sAl[(wm * 32 + i * 16) * LD + kk], LD);
            }
#pragma unroll
            for (int j = 0; j < 4; j++) {
                wmma::load_matrix_sync(bfh[j], &sBh[(wn * 64 + j * 16) * LD + kk], LD);
                wmma::load_matrix_sync(bfl[j], &sBl[(wn * 64 + j * 16) * LD + kk], LD);
            }
#pragma unroll
            for (int i = 0; i < 2; i++)
#pragma unroll
                for (int j = 0; j < 4; j++) {
                    wmma::mma_sync(acc[i][j], afh[i], bfl[j], acc[i][j]);
                    wmma::mma_sync(acc[i][j], afl[i], bfh[j], acc[i][j]);
                    wmma::mma_sync(acc[i][j], afh[i], bfh[j], acc[i][j]);
                }
        }
        __syncthreads();
    }
#undef LOAD_STAGE

#pragma unroll
    for (int i = 0; i < 2; i++)
#pragma unroll
        for (int j = 0; j < 4; j++)
            wmma::store_matrix_sync(
                C + (size_t)(m0 + wm * 32 + i * 16) * N + n0 + wn * 64 + j * 16,
                acc[i][j], N, wmma::mem_row_major);
}

// ---------------------------------------------------------------------------
// Fused RMSNorm + rope on q,k AND hi/lo bf16 pack of q,k,v into g_qkvh/g_qkvl.
// Block per (b,t) row, 512 thr = 16 warps; warp = head.
// ---------------------------------------------------------------------------
__global__ void __launch_bounds__(512) norm_rope_pack_kernel(
    const float* __restrict__ qkv, const float* __restrict__ rope,
    __nv_bfloat16* __restrict__ qh, __nv_bfloat16* __restrict__ ql)
{
    const int bt = blockIdx.x;
    const int t = bt & (Tv - 1);
    const int warp = threadIdx.x >> 5;
    const int lane = threadIdx.x & 31;

    const size_t base = (size_t)bt * QKV_N + warp * HDv;
    float c = rope[t * 32 + lane];
    float s = rope[Tv * 32 + t * 32 + lane];

#pragma unroll
    for (int p = 0; p < 2; p++) {   // q, k
        const float* ptr = qkv + base + p * Cv;
        float x1 = ptr[lane];
        float x2 = ptr[lane + 32];
        float ss = x1 * x1 + x2 * x2;
#pragma unroll
        for (int off = 16; off; off >>= 1)
            ss += __shfl_xor_sync(0xffffffffu, ss, off);
        float r = rsqrtf(ss * (1.0f / 64.0f) + 1.1920929e-07f);
        x1 *= r;
        x2 *= r;
        float y1 = x1 * c + x2 * s;
        float y2 = -x1 * s + x2 * c;
        split1(y1, qh + base + p * Cv + lane, ql + base + p * Cv + lane);
        split1(y2, qh + base + p * Cv + lane + 32, ql + base + p * Cv + lane + 32);
    }
    // v passthrough pack
    {
        const float* ptr = qkv + base + 2 * Cv;
        float v1 = ptr[lane];
        float v2 = ptr[lane + 32];
        split1(v1, qh + base + 2 * Cv + lane, ql + base + 2 * Cv + lane);
        split1(v2, qh + base + 2 * Cv + lane + 32, ql + base + 2 * Cv + lane + 32);
    }
}

// ---------------------------------------------------------------------------
// Flash attention: raw mma 3xBF16, register S/O, pre-split bf16 inputs,
// cp.async 2-stage double-buffered K/V.
// ---------------------------------------------------------------------------
__global__ void __launch_bounds__(256) flash_mma_kernel(
    const __nv_bfloat16* __restrict__ qh, const __nv_bfloat16* __restrict__ ql,
    float* __restrict__ y)
{
    constexpr int LDB = 72;
    constexpr int KVSTG = 4 * 64 * LDB;   // bf16 elems per stage (Kh Kl Vh Vl)
    extern __shared__ __align__(16) char smraw[];
    __nv_bfloat16* Qh = (__nv_bfloat16*)smraw;
    __nv_bfloat16* Ql = Qh + 128 * LDB;
    __nv_bfloat16* KV = Ql + 128 * LDB;

    const int qt = gridDim.x - 1 - blockIdx.x;
    const int bh = blockIdx.y;
    const int b = bh / Hv;
    const int h = bh % Hv;
    const int tid = threadIdx.x;
    const int wid = tid >> 5;
    const int lane = tid & 31;
    const int gid = lane >> 2;
    const int tig = lane & 3;

    const size_t rowbase = (size_t)b * Tv;
    const int q0 = qt * 128;

    const int arow = (lane & 7) + 8 * ((lane >> 3) & 1);
    const int acolo = 8 * (lane >> 4);
    const int brow = (lane & 7) + 8 * (lane >> 4);
    const int bcolo = 8 * ((lane >> 3) & 1);

    const unsigned QhS = (unsigned)__cvta_generic_to_shared(Qh);
    const unsigned QlS = (unsigned)__cvta_generic_to_shared(Ql);
    const unsigned KVS = (unsigned)__cvta_generic_to_shared(KV);

    float sc[8][4];
    float oc[8][4];
    unsigned qa[4];
    unsigned qb[4];
    unsigned ka[4];
    unsigned kb[4];
    unsigned va[4];
    unsigned vb[4];
    unsigned pah[4][4];
    unsigned pal[4][4];
    float mrow[2];
    float lrow[2];

    // K/V stage loader: hi/lo x K/V, 64 rows x 8 16B-chunks each
#define LOAD_KV(stg, jt)                                                      \
    do {                                                                      \
        unsigned sb = KVS + (unsigned)((stg) * KVSTG * 2);                    \
        const __nv_bfloat16* gkh = qh + (rowbase + (jt) * 64) * (size_t)QKV_N + Cv + h * HDv; \
        const __nv_bfloat16* gkl = ql + (rowbase + (jt) * 64) * (size_t)QKV_N + Cv + h * HDv; \
        for (int c = tid; c < 512; c += 256) {                                \
            int r = c >> 3;                                                   \
            int co = (c & 7) * 8;                                             \
            unsigned off = (unsigned)((r * LDB + co) * 2);                    \
            cp16(sb + off, gkh + (size_t)r * QKV_N + co);                     \
            cp16(sb + (unsigned)(64 * LDB * 2) + off, gkl + (size_t)r * QKV_N + co); \
            cp16(sb + (unsigned)(2 * 64 * LDB * 2) + off, gkh + (size_t)r * QKV_N + Cv + co); \
            cp16(sb + (unsigned)(3 * 64 * LDB * 2) + off, gkl + (size_t)r * QKV_N + Cv + co); \
        }                                                                     \
    } while (0)

    // Q load (cp.async) + first K/V stage, one group
    for (int c = tid; c < 1024; c += 256) {
        int r = c >> 3;
        int co = (c & 7) * 8;
        unsigned off = (unsigned)((r * LDB + co) * 2);
        cp16(QhS + off, qh + (rowbase + q0 + r) * (size_t)QKV_N + h * HDv + co);
        cp16(QlS + off, ql + (rowbase + q0 + r) * (size_t)QKV_N + h * HDv + co);
    }
    LOAD_KV(0, 0);
    cpcommit();

#pragma unroll
    for (int j = 0; j < 8; j++)
#pragma unroll
        for (int k = 0; k < 4; k++) oc[j][k] = 0.0f;

    mrow[0] = -1e30f;
    mrow[1] = -1e30f;
    lrow[0] = 0.0f;
    lrow[1] = 0.0f;
    const int r0g = q0 + wid * 16 + gid;
    const int r1g = r0g + 8;

    const int jt_max = 2 * qt + 1;
    for (int jt = 0; jt <= jt_max; jt++) {
        if (jt < jt_max) {
            LOAD_KV((jt + 1) & 1, jt + 1);
            cpcommit();
            cpwait1();
        } else {
            cpwait0();
        }
        __syncthreads();

        unsigned sb = KVS + (unsigned)((jt & 1) * KVSTG * 2);
        unsigned KhC = sb;
        unsigned KlC = sb + (unsigned)(64 * LDB * 2);
        unsigned VhC = sb + (unsigned)(2 * 64 * LDB * 2);
        unsigned VlC = sb + (unsigned)(3 * 64 * LDB * 2);

        // ---- S = Q K^T ----
#pragma unroll
        for (int j = 0; j < 8; j++)
#pragma unroll
            for (int k = 0; k < 4; k++) sc[j][k] = 0.0f;

#pragma unroll
        for (int t = 0; t < 4; t++) {
            unsigned qoff = (unsigned)(((wid * 16 + arow) * LDB + t * 16 + acolo) * 2);
            ldsm4(QhS + qoff, qa);
            ldsm4(QlS + qoff, qb);
#pragma unroll
            for (int g = 0; g < 4; g++) {
                unsigned koff = (unsigned)(((g * 16 + brow) * LDB + t * 16 + bcolo) * 2);
                ldsm4(KhC + koff, ka);
                ldsm4(KlC + koff, kb);
                mma_bf16(sc[2 * g], qa, kb[0], kb[1]);
                mma_bf16(sc[2 * g], qb, ka[0], ka[1]);
                mma_bf16(sc[2 * g], qa, ka[0], ka[1]);
                mma_bf16(sc[2 * g + 1], qa, kb[2], kb[3]);
                mma_bf16(sc[2 * g + 1], qb, ka[2], ka[3]);
                mma_bf16(sc[2 * g + 1], qa, ka[2], ka[3]);
            }
        }

        // ---- softmax in registers ----
        const bool maskp = (jt >= 2 * qt);
        float mt0 = -1e30f;
        float mt1 = -1e30f;
#pragma unroll
        for (int j = 0; j < 8; j++) {
            int c0 = jt * 64 + j * 8 + tig * 2;
            sc[j][0] *= 0.125f;
            sc[j][1] *= 0.125f;
            sc[j][2] *= 0.125f;
            sc[j][3] *= 0.125f;
            if (maskp) {
                if (c0 > r0g) sc[j][0] = -1e30f;
                if (c0 + 1 > r0g) sc[j][1] = -1e30f;
                if (c0 > r1g) sc[j][2] = -1e30f;
                if (c0 + 1 > r1g) sc[j][3] = -1e30f;
            }
            mt0 = fmaxf(mt0, fmaxf(sc[j][0], sc[j][1]));
            mt1 = fmaxf(mt1, fmaxf(sc[j][2], sc[j][3]));
        }
        mt0 = fmaxf(mt0, __shfl_xor_sync(0xffffffffu, mt0, 1));
        mt0 = fmaxf(mt0, __shfl_xor_sync(0xffffffffu, mt0, 2));
        mt1 = fmaxf(mt1, __shfl_xor_sync(0xffffffffu, mt1, 1));
        mt1 = fmaxf(mt1, __shfl_xor_sync(0xffffffffu, mt1, 2));

        float mn0 = fmaxf(mrow[0], mt0);
        float mn1 = fmaxf(mrow[1], mt1);
        float corr0 = expf(mrow[0] - mn0);
        float corr1 = expf(mrow[1] - mn1);

        float s0 = 0.0f;
        float s1 = 0.0f;
#pragma unroll
        for (int t = 0; t < 4; t++) {
            float p00 = expf(sc[2 * t][0] - mn0);
            float p01 = expf(sc[2 * t][1] - mn0);
            float p02 = expf(sc[2 * t][2] - mn1);
            float p03 = expf(sc[2 * t][3] - mn1);
            float p10 = expf(sc[2 * t + 1][0] - mn0);
            float p11 = expf(sc[2 * t + 1][1] - mn0);
            float p12 = expf(sc[2 * t + 1][2] - mn1);
            float p13 = expf(sc[2 * t + 1][3] - mn1);
            s0 += p00 + p01 + p10 + p11;
            s1 += p02 + p03 + p12 + p13;
            packsplit(p00, p01, pah[t][0], pal[t][0]);
            packsplit(p02, p03, pah[t][1], pal[t][1]);
            packsplit(p10, p11, pah[t][2], pal[t][2]);
            packsplit(p12, p13, pah[t][3], pal[t][3]);
        }
        s0 += __shfl_xor_sync(0xffffffffu, s0, 1);
        s0 += __shfl_xor_sync(0xffffffffu, s0, 2);
        s1 += __shfl_xor_sync(0xffffffffu, s1, 1);
        s1 += __shfl_xor_sync(0xffffffffu, s1, 2);

        lrow[0] = lrow[0] * corr0 + s0;
        lrow[1] = lrow[1] * corr1 + s1;
        mrow[0] = mn0;
        mrow[1] = mn1;
#pragma unroll
        for (int j = 0; j < 8; j++) {
            oc[j][0] *= corr0;
            oc[j][1] *= corr0;
            oc[j][2] *= corr1;
            oc[j][3] *= corr1;
        }

        // ---- O += P V ----
#pragma unroll
        for (int t = 0; t < 4; t++) {
#pragma unroll
            for (int n = 0; n < 4; n++) {
                unsigned voff = (unsigned)(((t * 16 + arow) * LDB + n * 16 + acolo) * 2);
                ldsm4t(VhC + voff, va);
                ldsm4t(VlC + voff, vb);
                mma_bf16(oc[2 * n], pah[t], vb[0], vb[1]);
                mma_bf16(oc[2 * n], pal[t], va[0], va[1]);
                mma_bf16(oc[2 * n], pah[t], va[0], va[1]);
                mma_bf16(oc[2 * n + 1], pah[t], vb[2], vb[3]);
                mma_bf16(oc[2 * n + 1], pal[t], va[2], va[3]);
                mma_bf16(oc[2 * n + 1], pah[t], va[2], va[3]);
            }
        }
        __syncthreads();   // all warps done with this stage before its reuse
    }
#undef LOAD_KV

    float i0 = 1.0f / lrow[0];
    float i1 = 1.0f / lrow[1];
#pragma unroll
    for (int j = 0; j < 8; j++) {
        int col = h * HDv + j * 8 + tig * 2;
        *(float2*)&y[(rowbase + r0g) * (size_t)Cv + col] =
            make_float2(oc[j][0] * i0, oc[j][1] * i0);
        *(float2*)&y[(rowbase + r1g) * (size_t)Cv + col] =
            make_float2(oc[j][2] * i1, oc[j][3] * i1);
    }
}

// ---------------------------------------------------------------------------
extern "C" void kernel_launch(void* const* d_in, const int* in_sizes, int n_in,
                              void* d_out, int out_size)
{
    const float* x = (const float*)d_in[0];
    const float* w_attn = (const float*)d_in[1];
    const float* w_proj = (const float*)d_in[2];
    float* out = (float*)d_out;

    float* qkv_p = nullptr;
    float* y_p = nullptr;
    float* rope_p = nullptr;
    __nv_bfloat16* ah_p = nullptr;
    __nv_bfloat16* al_p = nullptr;
    __nv_bfloat16* wh_p = nullptr;
    __nv_bfloat16* wl_p = nullptr;
    __nv_bfloat16* qh_p = nullptr;
    __nv_bfloat16* ql_p = nullptr;
    cudaGetSymbolAddress((void**)&qkv_p, g_qkv);
    cudaGetSymbolAddress((void**)&y_p, g_y);
    cudaGetSymbolAddress((void**)&rope_p, g_rope);
    cudaGetSymbolAddress((void**)&ah_p, g_ah);
    cudaGetSymbolAddress((void**)&al_p, g_al);
    cudaGetSymbolAddress((void**)&wh_p, g_wh);
    cudaGetSymbolAddress((void**)&wl_p, g_wl);
    cudaGetSymbolAddress((void**)&qh_p, g_qkvh);
    cudaGetSymbolAddress((void**)&ql_p, g_qkvl);

    const int GEMM_SMEM = 2 * 4 * 128 * 40 * (int)sizeof(__nv_bfloat16);  // 81920 B
    cudaFuncSetAttribute(gemm_bf16_pre, cudaFuncAttributeMaxDynamicSharedMemorySize, GEMM_SMEM);

    rope_table_kernel<<<(Tv * 32 + 255) / 256, 256>>>(rope_p);

    pack_split_kernel<<<(Mv * Cv / 4 + 255) / 256, 256>>>(x, ah_p, al_p, Mv * Cv / 4);
    pack_split_kernel<<<(QKV_N * Cv / 4 + 255) / 256, 256>>>(w_attn, wh_p, wl_p, QKV_N * Cv / 4);
    pack_split_kernel<<<(Cv * Cv / 4 + 255) / 256, 256>>>(
        w_proj, wh_p + QKV_N * Cv, wl_p + QKV_N * Cv, Cv * Cv / 4);

    // qkv = x @ w_attn^T
    gemm_bf16_pre<<<dim3(QKV_N / 128, Mv / 128), 256, GEMM_SMEM>>>(
        ah_p, al_p, wh_p, wl_p, qkv_p, Mv, QKV_N, Cv);

    // norm + rope + split pack of q,k,v
    norm_rope_pack_kernel<<<Mv, 512>>>(qkv_p, rope_p, qh_p, ql_p);

    // flash (pre-split inputs, cp.async double-buffered K/V)
    const int FLASH_SMEM = (2 * 128 * 72 + 8 * 64 * 72) * (int)sizeof(__nv_bfloat16);  // 110592 B
    cudaFuncSetAttribute(flash_mma_kernel, cudaFuncAttributeMaxDynamicSharedMemorySize, FLASH_SMEM);
    flash_mma_kernel<<<dim3(Tv / 128, Bv * Hv), 256, FLASH_SMEM>>>(qh_p, ql_p, y_p);

    // pack y, then out = y @ w_proj^T
    pack_split_kernel<<<(Mv * Cv / 4 + 255) / 256, 256>>>(y_p, ah_p, al_p, Mv * Cv / 4);
    gemm_bf16_pre<<<dim3(Cv / 128, Mv / 128), 256, GEMM_SMEM>>>(
        ah_p, al_p, wh_p + QKV_N * Cv, wl_p + QKV_N * Cv, out, Mv, Cv, Cv);
}